// round 3
// baseline (speedup 1.0000x reference)
#include <cuda_runtime.h>

#define Bb 4
#define Ss 2048
#define Dd 1024
#define Hh 16
#define HDd 64
#define Mrows (Bb*Ss)   // 8192

// Scratch (device globals — no runtime allocation allowed)
__device__ float g_Q[Mrows*Dd];
__device__ float g_K[Mrows*Dd];
__device__ float g_V[Mrows*Dd];
__device__ float g_C[Mrows*Dd];

// ---------------------------------------------------------------------------
// C[M,1024] = A[M,1024] @ W[1024,1024] (+ optional bias), fp32
// 64x64 tile per block, K-tile 16, 256 threads, 4x4 micro-tile per thread.
// ---------------------------------------------------------------------------
__global__ __launch_bounds__(256) void gemm_kernel(
    const float* __restrict__ A, const float* __restrict__ W,
    const float* __restrict__ bias, float* __restrict__ C)
{
    const int K = Dd, N = Dd;
    __shared__ float As[16][65];   // transposed: As[k][m], padded
    __shared__ float Bs[16][65];   // Bs[k][n], padded

    int t  = threadIdx.x;
    int m0 = blockIdx.y * 64;
    int n0 = blockIdx.x * 64;
    int ty = t >> 4;               // 0..15
    int tx = t & 15;               // 0..15

    float acc[4][4] = {};

    for (int k0 = 0; k0 < K; k0 += 16) {
        #pragma unroll
        for (int e = 0; e < 4; e++) {
            int idx = t + e * 256;           // 0..1023
            int row = idx >> 4;              // 0..63
            int col = idx & 15;              // 0..15
            As[col][row] = A[(size_t)(m0 + row) * K + k0 + col];
        }
        #pragma unroll
        for (int e = 0; e < 4; e++) {
            int idx = t + e * 256;
            int row = idx >> 6;              // 0..15
            int col = idx & 63;              // 0..63
            Bs[row][col] = W[(size_t)(k0 + row) * N + n0 + col];
        }
        __syncthreads();

        #pragma unroll
        for (int kk = 0; kk < 16; kk++) {
            float a[4], b[4];
            #pragma unroll
            for (int i = 0; i < 4; i++) a[i] = As[kk][ty * 4 + i];
            #pragma unroll
            for (int j = 0; j < 4; j++) b[j] = Bs[kk][tx * 4 + j];
            #pragma unroll
            for (int i = 0; i < 4; i++)
                #pragma unroll
                for (int j = 0; j < 4; j++)
                    acc[i][j] = fmaf(a[i], b[j], acc[i][j]);
        }
        __syncthreads();
    }

    #pragma unroll
    for (int i = 0; i < 4; i++) {
        int m = m0 + ty * 4 + i;
        #pragma unroll
        for (int j = 0; j < 4; j++) {
            int n = n0 + tx * 4 + j;
            float v = acc[i][j];
            if (bias) v += bias[n];
            C[(size_t)m * N + n] = v;
        }
    }
}

// ---------------------------------------------------------------------------
// Causal flash attention, fp32, head_dim = 64, quad-lane layout.
// Grid: (S/64 query tiles, B*H). 256 threads = 64 queries x 4 lanes.
// Lane di = t&3 owns dims [di*16, di*16+16) of query (t>>2): q[16], acc[16]
// in registers. Score dot-product reduced across the quad via shfl_xor.
//
// DEADLOCK FIX (R2): the j loop bound is now warp-uniform (always 64).
// Every lane executes every __shfl_xor_sync (full-mask legal); the causal
// mask only predicates the softmax-state update. Previously jmax varied
// per-lane within a warp while the shuffles used a full mask -> UB/hang.
// ---------------------------------------------------------------------------
__global__ __launch_bounds__(256) void attn_kernel(
    const float* __restrict__ Q, const float* __restrict__ K,
    const float* __restrict__ V, float* __restrict__ ctx)
{
    __shared__ float Ks[64][64];
    __shared__ float Vs[64][64];

    int t   = threadIdx.x;
    int tq  = t >> 2;              // local query 0..63
    int di  = t & 3;               // dim-slice 0..3
    int dof = di * 16;
    int qt  = blockIdx.x;
    int bh  = blockIdx.y;
    int b   = bh >> 4;             // / H
    int h   = bh & 15;             // % H
    int qg  = qt * 64 + tq;        // global query row within sequence
    const float scale = 0.125f;    // 1/sqrt(64)

    float q[16];
    const float* qptr = Q + ((size_t)(b * Ss + qg)) * Dd + h * HDd + dof;
    #pragma unroll
    for (int d = 0; d < 16; d++) q[d] = qptr[d];

    float m = -1e30f, l = 0.f;
    float acc[16] = {};

    for (int kt = 0; kt <= qt; kt++) {
        const bool diag = (kt == qt);
        const float* kbase = K + ((size_t)(b * Ss + kt * 64)) * Dd + h * HDd;
        const float* vbase = V + ((size_t)(b * Ss + kt * 64)) * Dd + h * HDd;
        // Cooperative coalesced tile loads: 64x64 by 256 threads (16 ea)
        #pragma unroll
        for (int e = 0; e < 16; e++) {
            int idx = t + e * 256;
            int r = idx >> 6;
            int c = idx & 63;
            Ks[r][c] = kbase[(size_t)r * Dd + c];
            Vs[r][c] = vbase[(size_t)r * Dd + c];
        }
        __syncthreads();

        // Warp-uniform loop: ALL lanes run all 64 iterations and all shuffles.
        for (int j = 0; j < 64; j++) {
            float p4 = 0.f;
            #pragma unroll
            for (int d = 0; d < 16; d++) p4 = fmaf(q[d], Ks[j][dof + d], p4);
            p4 += __shfl_xor_sync(0xffffffffu, p4, 1);
            p4 += __shfl_xor_sync(0xffffffffu, p4, 2);
            bool active = !diag || (j <= tq);     // causal predicate
            if (active) {
                float s = p4 * scale;
                if (s > m) {
                    float alpha = __expf(m - s);
                    l *= alpha;
                    #pragma unroll
                    for (int d = 0; d < 16; d++) acc[d] *= alpha;
                    m = s;
                }
                float p = __expf(s - m);
                l += p;
                #pragma unroll
                for (int d = 0; d < 16; d++) acc[d] = fmaf(p, Vs[j][dof + d], acc[d]);
            }
        }
        __syncthreads();
    }

    float inv = 1.f / l;
    float* optr = ctx + ((size_t)(b * Ss + qg)) * Dd + h * HDd + dof;
    #pragma unroll
    for (int d = 0; d < 16; d++) optr[d] = acc[d] * inv;
}

// ---------------------------------------------------------------------------
extern "C" void kernel_launch(void* const* d_in, const int* in_sizes, int n_in,
                              void* d_out, int out_size)
{
    const float* x  = (const float*)d_in[0];
    const float* Wq = (const float*)d_in[1];
    const float* Wk = (const float*)d_in[2];
    const float* Wv = (const float*)d_in[3];
    const float* Wo = (const float*)d_in[4];
    const float* bo = (const float*)d_in[5];
    float* out = (float*)d_out;

    float *Qp, *Kp, *Vp, *Cp;
    cudaGetSymbolAddress((void**)&Qp, g_Q);
    cudaGetSymbolAddress((void**)&Kp, g_K);
    cudaGetSymbolAddress((void**)&Vp, g_V);
    cudaGetSymbolAddress((void**)&Cp, g_C);

    dim3 gg(Dd / 64, Mrows / 64);       // (16, 128)
    gemm_kernel<<<gg, 256>>>(x, Wq, nullptr, Qp);
    gemm_kernel<<<gg, 256>>>(x, Wk, nullptr, Kp);
    gemm_kernel<<<gg, 256>>>(x, Wv, nullptr, Vp);

    attn_kernel<<<dim3(Ss / 64, Bb * Hh), 256>>>(Qp, Kp, Vp, Cp);

    gemm_kernel<<<gg, 256>>>(Cp, Wo, bo, out);
}

// round 5
// speedup vs baseline: 1.1751x; 1.1751x over previous
#include <cuda_runtime.h>
#include <cuda_bf16.h>
#include <cstdint>

#define Bb 4
#define Ss 2048
#define Dd 1024
#define Hh 16
#define HDd 64
#define Mrows (Bb*Ss)   // 8192

// ---------------- scratch (device globals; no runtime allocation) ----------
__device__ float g_Q[Mrows*Dd];
__device__ float g_K[Mrows*Dd];
__device__ float g_V[Mrows*Dd];
__device__ float g_C[Mrows*Dd];
__device__ __nv_bfloat16 g_ah[Mrows*Dd];   // activation hi (x, later ctx)
__device__ __nv_bfloat16 g_al[Mrows*Dd];   // activation lo
__device__ __nv_bfloat16 g_wh[Dd*Dd];      // weight hi (reused per GEMM)
__device__ __nv_bfloat16 g_wl[Dd*Dd];      // weight lo

// ---------------------------------------------------------------------------
// Split fp32 -> (hi, lo) bf16 pair:  x ~= hi + lo, |err| ~ 2^-18 |x|
// ---------------------------------------------------------------------------
__global__ __launch_bounds__(256) void split_kernel(
    const float* __restrict__ in, __nv_bfloat16* __restrict__ hi,
    __nv_bfloat16* __restrict__ lo, int n)
{
    int i = blockIdx.x * 256 + threadIdx.x;
    if (i < n) {
        float x = in[i];
        __nv_bfloat16 h = __float2bfloat16(x);
        float r = x - __bfloat162float(h);
        hi[i] = h;
        lo[i] = __float2bfloat16(r);
    }
}

// ---------------------------------------------------------------------------
// C[M,1024] = (Ah+Al) @ (Wh+Wl) + bias, via 3 bf16 tensor-core products:
//   Ah@Wh + Ah@Wl + Al@Wh   (fp32 accumulate)
// Block tile 128x64, K-tile 32, 256 threads (8 warps, 4x2), warp tile 32x32.
// mma.sync m16n8k16 bf16. W tile staged transposed [n][k] in smem.
// ---------------------------------------------------------------------------
#define AS 40   // smem stride in halves (80B: 16B-aligned rows, bank-staggered)

#define MMA16816(Cf, Af, Bf) \
    asm volatile("mma.sync.aligned.m16n8k16.row.col.f32.bf16.bf16.f32 " \
        "{%0,%1,%2,%3}, {%4,%5,%6,%7}, {%8,%9}, {%0,%1,%2,%3};" \
        : "+f"(Cf[0]), "+f"(Cf[1]), "+f"(Cf[2]), "+f"(Cf[3]) \
        : "r"(Af[0]), "r"(Af[1]), "r"(Af[2]), "r"(Af[3]), \
          "r"(Bf[0]), "r"(Bf[1]))

__global__ __launch_bounds__(256) void gemm_bf16_kernel(
    const __nv_bfloat16* __restrict__ Ah, const __nv_bfloat16* __restrict__ Al,
    const __nv_bfloat16* __restrict__ Wh, const __nv_bfloat16* __restrict__ Wl,
    const float* __restrict__ bias, float* __restrict__ C)
{
    __shared__ __nv_bfloat16 sAh[128][AS];
    __shared__ __nv_bfloat16 sAl[128][AS];
    __shared__ __nv_bfloat16 sWh[64][AS];   // transposed: [n][k]
    __shared__ __nv_bfloat16 sWl[64][AS];

    int t    = threadIdx.x;
    int lane = t & 31, wid = t >> 5;
    int wm   = wid >> 1, wn = wid & 1;      // warp grid 4(M) x 2(N)
    int m0   = blockIdx.y * 128, n0 = blockIdx.x * 64;
    int tg   = lane & 3, gp = lane >> 2;    // quad id, group id

    float acc[2][4][4] = {};                // [mi][ni][c0..c3]

    for (int k0 = 0; k0 < Dd; k0 += 32) {
        // ---- stage A tiles (128x32 halves each): 2 float4 per thread per tile
        {
            int r   = t >> 1;               // 0..127
            int c16 = (t & 1) * 16;         // half offset 0 / 16
            const float4* ga = reinterpret_cast<const float4*>(
                Ah + (size_t)(m0 + r) * Dd + k0 + c16);
            float4 v0 = ga[0], v1 = ga[1];
            *reinterpret_cast<float4*>(&sAh[r][c16])     = v0;
            *reinterpret_cast<float4*>(&sAh[r][c16 + 8]) = v1;
            const float4* gb = reinterpret_cast<const float4*>(
                Al + (size_t)(m0 + r) * Dd + k0 + c16);
            float4 u0 = gb[0], u1 = gb[1];
            *reinterpret_cast<float4*>(&sAl[r][c16])     = u0;
            *reinterpret_cast<float4*>(&sAl[r][c16 + 8]) = u1;
        }
        // ---- stage W tiles (32x64), written transposed [n][k]
        #pragma unroll
        for (int e = 0; e < 4; e++) {
            int idx = t + e * 256;          // 0..1023
            int kr  = idx >> 5;             // k row 0..31
            int c2  = (idx & 31) * 2;       // n offset 0..62
            __nv_bfloat162 vh = *reinterpret_cast<const __nv_bfloat162*>(
                Wh + (size_t)(k0 + kr) * Dd + n0 + c2);
            sWh[c2][kr] = vh.x; sWh[c2 + 1][kr] = vh.y;
            __nv_bfloat162 vl = *reinterpret_cast<const __nv_bfloat162*>(
                Wl + (size_t)(k0 + kr) * Dd + n0 + c2);
            sWl[c2][kr] = vl.x; sWl[c2 + 1][kr] = vl.y;
        }
        __syncthreads();

        #pragma unroll
        for (int kh = 0; kh < 2; kh++) {
            int kc = kh * 16 + tg * 2;
            // A fragments (hi and lo) for both 16-row tiles of this warp
            uint32_t fah[2][4], fal[2][4];
            #pragma unroll
            for (int mi = 0; mi < 2; mi++) {
                int r1 = wm * 32 + mi * 16 + gp;
                fah[mi][0] = *reinterpret_cast<const uint32_t*>(&sAh[r1][kc]);
                fah[mi][1] = *reinterpret_cast<const uint32_t*>(&sAh[r1 + 8][kc]);
                fah[mi][2] = *reinterpret_cast<const uint32_t*>(&sAh[r1][kc + 8]);
                fah[mi][3] = *reinterpret_cast<const uint32_t*>(&sAh[r1 + 8][kc + 8]);
                fal[mi][0] = *reinterpret_cast<const uint32_t*>(&sAl[r1][kc]);
                fal[mi][1] = *reinterpret_cast<const uint32_t*>(&sAl[r1 + 8][kc]);
                fal[mi][2] = *reinterpret_cast<const uint32_t*>(&sAl[r1][kc + 8]);
                fal[mi][3] = *reinterpret_cast<const uint32_t*>(&sAl[r1 + 8][kc + 8]);
            }
            // B fragments (hi and lo) for the 4 n8 tiles of this warp
            uint32_t fbh[4][2], fbl[4][2];
            #pragma unroll
            for (int ni = 0; ni < 4; ni++) {
                int cn = wn * 32 + ni * 8 + gp;
                fbh[ni][0] = *reinterpret_cast<const uint32_t*>(&sWh[cn][kc]);
                fbh[ni][1] = *reinterpret_cast<const uint32_t*>(&sWh[cn][kc + 8]);
                fbl[ni][0] = *reinterpret_cast<const uint32_t*>(&sWl[cn][kc]);
                fbl[ni][1] = *reinterpret_cast<const uint32_t*>(&sWl[cn][kc + 8]);
            }
            #pragma unroll
            for (int mi = 0; mi < 2; mi++)
                #pragma unroll
                for (int ni = 0; ni < 4; ni++) {
                    MMA16816(acc[mi][ni], fah[mi], fbh[ni]);   // hi*hi
                    MMA16816(acc[mi][ni], fah[mi], fbl[ni]);   // hi*lo
                    MMA16816(acc[mi][ni], fal[mi], fbh[ni]);   // lo*hi
                }
        }
        __syncthreads();
    }

    // ---- epilogue
    #pragma unroll
    for (int mi = 0; mi < 2; mi++) {
        int r1 = m0 + wm * 32 + mi * 16 + gp;
        #pragma unroll
        for (int ni = 0; ni < 4; ni++) {
            int cn = n0 + wn * 32 + ni * 8 + tg * 2;
            float b0 = bias ? bias[cn] : 0.f;
            float b1 = bias ? bias[cn + 1] : 0.f;
            C[(size_t)r1 * Dd + cn]           = acc[mi][ni][0] + b0;
            C[(size_t)r1 * Dd + cn + 1]       = acc[mi][ni][1] + b1;
            C[(size_t)(r1 + 8) * Dd + cn]     = acc[mi][ni][2] + b0;
            C[(size_t)(r1 + 8) * Dd + cn + 1] = acc[mi][ni][3] + b1;
        }
    }
}

// ---------------------------------------------------------------------------
// Causal flash attention, fp32, head_dim = 64, quad-lane layout (unchanged
// from R2 pass: warp-uniform inner loop, full-mask shuffles, predicated
// softmax update).
// ---------------------------------------------------------------------------
__global__ __launch_bounds__(256) void attn_kernel(
    const float* __restrict__ Q, const float* __restrict__ K,
    const float* __restrict__ V, float* __restrict__ ctx)
{
    __shared__ float Ks[64][64];
    __shared__ float Vs[64][64];

    int t   = threadIdx.x;
    int tq  = t >> 2;
    int di  = t & 3;
    int dof = di * 16;
    int qt  = blockIdx.x;
    int bh  = blockIdx.y;
    int b   = bh >> 4;
    int h   = bh & 15;
    int qg  = qt * 64 + tq;
    const float scale = 0.125f;

    float q[16];
    const float* qptr = Q + ((size_t)(b * Ss + qg)) * Dd + h * HDd + dof;
    #pragma unroll
    for (int d = 0; d < 16; d++) q[d] = qptr[d];

    float m = -1e30f, l = 0.f;
    float acc[16] = {};

    for (int kt = 0; kt <= qt; kt++) {
        const bool diag = (kt == qt);
        const float* kbase = K + ((size_t)(b * Ss + kt * 64)) * Dd + h * HDd;
        const float* vbase = V + ((size_t)(b * Ss + kt * 64)) * Dd + h * HDd;
        #pragma unroll
        for (int e = 0; e < 16; e++) {
            int idx = t + e * 256;
            int r = idx >> 6;
            int c = idx & 63;
            Ks[r][c] = kbase[(size_t)r * Dd + c];
            Vs[r][c] = vbase[(size_t)r * Dd + c];
        }
        __syncthreads();

        for (int j = 0; j < 64; j++) {
            float p4 = 0.f;
            #pragma unroll
            for (int d = 0; d < 16; d++) p4 = fmaf(q[d], Ks[j][dof + d], p4);
            p4 += __shfl_xor_sync(0xffffffffu, p4, 1);
            p4 += __shfl_xor_sync(0xffffffffu, p4, 2);
            bool active = !diag || (j <= tq);
            if (active) {
                float s = p4 * scale;
                if (s > m) {
                    float alpha = __expf(m - s);
                    l *= alpha;
                    #pragma unroll
                    for (int d = 0; d < 16; d++) acc[d] *= alpha;
                    m = s;
                }
                float p = __expf(s - m);
                l += p;
                #pragma unroll
                for (int d = 0; d < 16; d++) acc[d] = fmaf(p, Vs[j][dof + d], acc[d]);
            }
        }
        __syncthreads();
    }

    float inv = 1.f / l;
    float* optr = ctx + ((size_t)(b * Ss + qg)) * Dd + h * HDd + dof;
    #pragma unroll
    for (int d = 0; d < 16; d++) optr[d] = acc[d] * inv;
}

// ---------------------------------------------------------------------------
extern "C" void kernel_launch(void* const* d_in, const int* in_sizes, int n_in,
                              void* d_out, int out_size)
{
    const float* x  = (const float*)d_in[0];
    const float* Wq = (const float*)d_in[1];
    const float* Wk = (const float*)d_in[2];
    const float* Wv = (const float*)d_in[3];
    const float* Wo = (const float*)d_in[4];
    const float* bo = (const float*)d_in[5];
    float* out = (float*)d_out;

    float *Qp, *Kp, *Vp, *Cp;
    __nv_bfloat16 *ah, *al, *wh, *wl;
    cudaGetSymbolAddress((void**)&Qp, g_Q);
    cudaGetSymbolAddress((void**)&Kp, g_K);
    cudaGetSymbolAddress((void**)&Vp, g_V);
    cudaGetSymbolAddress((void**)&Cp, g_C);
    cudaGetSymbolAddress((void**)&ah, g_ah);
    cudaGetSymbolAddress((void**)&al, g_al);
    cudaGetSymbolAddress((void**)&wh, g_wh);
    cudaGetSymbolAddress((void**)&wl, g_wl);

    const int NX = Mrows * Dd;      // 8M
    const int NW = Dd * Dd;         // 1M
    dim3 gg(Dd / 64, Mrows / 128);  // (16, 64)

    // split activations once; reuse wh/wl per weight (stream-ordered)
    split_kernel<<<NX / 256, 256>>>(x, ah, al, NX);

    split_kernel<<<NW / 256, 256>>>(Wq, wh, wl, NW);
    gemm_bf16_kernel<<<gg, 256>>>(ah, al, wh, wl, nullptr, Qp);
    split_kernel<<<NW / 256, 256>>>(Wk, wh, wl, NW);
    gemm_bf16_kernel<<<gg, 256>>>(ah, al, wh, wl, nullptr, Kp);
    split_kernel<<<NW / 256, 256>>>(Wv, wh, wl, NW);
    gemm_bf16_kernel<<<gg, 256>>>(ah, al, wh, wl, nullptr, Vp);

    attn_kernel<<<dim3(Ss / 64, Bb * Hh), 256>>>(Qp, Kp, Vp, Cp);

    split_kernel<<<NX / 256, 256>>>(Cp, ah, al, NX);
    split_kernel<<<NW / 256, 256>>>(Wo, wh, wl, NW);
    gemm_bf16_kernel<<<gg, 256>>>(ah, al, wh, wl, bo, out);
}

// round 6
// speedup vs baseline: 3.1298x; 2.6635x over previous
#include <cuda_runtime.h>
#include <cuda_bf16.h>
#include <cstdint>

#define Bb 4
#define Ss 2048
#define Dd 1024
#define Hh 16
#define HDd 64
#define Mrows (Bb*Ss)   // 8192

// ---------------- scratch (device globals; no runtime allocation) ----------
__device__ float g_Q[Mrows*Dd];
__device__ float g_K[Mrows*Dd];
__device__ float g_V[Mrows*Dd];
__device__ float g_C[Mrows*Dd];
__device__ __nv_bfloat16 g_ah[Mrows*Dd];   // activation hi (x, later ctx)
__device__ __nv_bfloat16 g_al[Mrows*Dd];   // activation lo
__device__ __nv_bfloat16 g_wh[Dd*Dd];      // weight hi (reused per GEMM)
__device__ __nv_bfloat16 g_wl[Dd*Dd];      // weight lo

#define MMA16816(Cf, Af, Bf) \
    asm volatile("mma.sync.aligned.m16n8k16.row.col.f32.bf16.bf16.f32 " \
        "{%0,%1,%2,%3}, {%4,%5,%6,%7}, {%8,%9}, {%0,%1,%2,%3};" \
        : "+f"(Cf[0]), "+f"(Cf[1]), "+f"(Cf[2]), "+f"(Cf[3]) \
        : "r"(Af[0]), "r"(Af[1]), "r"(Af[2]), "r"(Af[3]), \
          "r"(Bf[0]), "r"(Bf[1]))

// split two fp32 into packed bf16x2 hi and lo words (low element in low bits)
__device__ __forceinline__ void split2(float x, float y, uint32_t& hi, uint32_t& lo)
{
    __nv_bfloat16 hx = __float2bfloat16(x), hy = __float2bfloat16(y);
    float rx = x - __bfloat162float(hx);
    float ry = y - __bfloat162float(hy);
    __nv_bfloat162 h2(hx, hy);
    __nv_bfloat162 l2(__float2bfloat16(rx), __float2bfloat16(ry));
    hi = *reinterpret_cast<uint32_t*>(&h2);
    lo = *reinterpret_cast<uint32_t*>(&l2);
}

// ---------------------------------------------------------------------------
// Split fp32 -> (hi, lo) bf16 pair (global pass, for GEMM operands)
// ---------------------------------------------------------------------------
__global__ __launch_bounds__(256) void split_kernel(
    const float* __restrict__ in, __nv_bfloat16* __restrict__ hi,
    __nv_bfloat16* __restrict__ lo, int n)
{
    int i = blockIdx.x * 256 + threadIdx.x;
    if (i < n) {
        float x = in[i];
        __nv_bfloat16 h = __float2bfloat16(x);
        float r = x - __bfloat162float(h);
        hi[i] = h;
        lo[i] = __float2bfloat16(r);
    }
}

// ---------------------------------------------------------------------------
// C[M,1024] = (Ah+Al) @ (Wh+Wl) + bias, 3-term bf16 split GEMM (R5, passing)
// ---------------------------------------------------------------------------
#define AS 40

__global__ __launch_bounds__(256) void gemm_bf16_kernel(
    const __nv_bfloat16* __restrict__ Ah, const __nv_bfloat16* __restrict__ Al,
    const __nv_bfloat16* __restrict__ Wh, const __nv_bfloat16* __restrict__ Wl,
    const float* __restrict__ bias, float* __restrict__ C)
{
    __shared__ __nv_bfloat16 sAh[128][AS];
    __shared__ __nv_bfloat16 sAl[128][AS];
    __shared__ __nv_bfloat16 sWh[64][AS];   // transposed: [n][k]
    __shared__ __nv_bfloat16 sWl[64][AS];

    int t    = threadIdx.x;
    int lane = t & 31, wid = t >> 5;
    int wm   = wid >> 1, wn = wid & 1;
    int m0   = blockIdx.y * 128, n0 = blockIdx.x * 64;
    int tg   = lane & 3, gp = lane >> 2;

    float acc[2][4][4] = {};

    for (int k0 = 0; k0 < Dd; k0 += 32) {
        {
            int r   = t >> 1;
            int c16 = (t & 1) * 16;
            const float4* ga = reinterpret_cast<const float4*>(
                Ah + (size_t)(m0 + r) * Dd + k0 + c16);
            float4 v0 = ga[0], v1 = ga[1];
            *reinterpret_cast<float4*>(&sAh[r][c16])     = v0;
            *reinterpret_cast<float4*>(&sAh[r][c16 + 8]) = v1;
            const float4* gb = reinterpret_cast<const float4*>(
                Al + (size_t)(m0 + r) * Dd + k0 + c16);
            float4 u0 = gb[0], u1 = gb[1];
            *reinterpret_cast<float4*>(&sAl[r][c16])     = u0;
            *reinterpret_cast<float4*>(&sAl[r][c16 + 8]) = u1;
        }
        #pragma unroll
        for (int e = 0; e < 4; e++) {
            int idx = t + e * 256;
            int kr  = idx >> 5;
            int c2  = (idx & 31) * 2;
            __nv_bfloat162 vh = *reinterpret_cast<const __nv_bfloat162*>(
                Wh + (size_t)(k0 + kr) * Dd + n0 + c2);
            sWh[c2][kr] = vh.x; sWh[c2 + 1][kr] = vh.y;
            __nv_bfloat162 vl = *reinterpret_cast<const __nv_bfloat162*>(
                Wl + (size_t)(k0 + kr) * Dd + n0 + c2);
            sWl[c2][kr] = vl.x; sWl[c2 + 1][kr] = vl.y;
        }
        __syncthreads();

        #pragma unroll
        for (int kh = 0; kh < 2; kh++) {
            int kc = kh * 16 + tg * 2;
            uint32_t fah[2][4], fal[2][4];
            #pragma unroll
            for (int mi = 0; mi < 2; mi++) {
                int r1 = wm * 32 + mi * 16 + gp;
                fah[mi][0] = *reinterpret_cast<const uint32_t*>(&sAh[r1][kc]);
                fah[mi][1] = *reinterpret_cast<const uint32_t*>(&sAh[r1 + 8][kc]);
                fah[mi][2] = *reinterpret_cast<const uint32_t*>(&sAh[r1][kc + 8]);
                fah[mi][3] = *reinterpret_cast<const uint32_t*>(&sAh[r1 + 8][kc + 8]);
                fal[mi][0] = *reinterpret_cast<const uint32_t*>(&sAl[r1][kc]);
                fal[mi][1] = *reinterpret_cast<const uint32_t*>(&sAl[r1 + 8][kc]);
                fal[mi][2] = *reinterpret_cast<const uint32_t*>(&sAl[r1][kc + 8]);
                fal[mi][3] = *reinterpret_cast<const uint32_t*>(&sAl[r1 + 8][kc + 8]);
            }
            uint32_t fbh[4][2], fbl[4][2];
            #pragma unroll
            for (int ni = 0; ni < 4; ni++) {
                int cn = wn * 32 + ni * 8 + gp;
                fbh[ni][0] = *reinterpret_cast<const uint32_t*>(&sWh[cn][kc]);
                fbh[ni][1] = *reinterpret_cast<const uint32_t*>(&sWh[cn][kc + 8]);
                fbl[ni][0] = *reinterpret_cast<const uint32_t*>(&sWl[cn][kc]);
                fbl[ni][1] = *reinterpret_cast<const uint32_t*>(&sWl[cn][kc + 8]);
            }
            #pragma unroll
            for (int mi = 0; mi < 2; mi++)
                #pragma unroll
                for (int ni = 0; ni < 4; ni++) {
                    MMA16816(acc[mi][ni], fah[mi], fbh[ni]);
                    MMA16816(acc[mi][ni], fah[mi], fbl[ni]);
                    MMA16816(acc[mi][ni], fal[mi], fbh[ni]);
                }
        }
        __syncthreads();
    }

    #pragma unroll
    for (int mi = 0; mi < 2; mi++) {
        int r1 = m0 + wm * 32 + mi * 16 + gp;
        #pragma unroll
        for (int ni = 0; ni < 4; ni++) {
            int cn = n0 + wn * 32 + ni * 8 + tg * 2;
            float b0 = bias ? bias[cn] : 0.f;
            float b1 = bias ? bias[cn + 1] : 0.f;
            C[(size_t)r1 * Dd + cn]           = acc[mi][ni][0] + b0;
            C[(size_t)r1 * Dd + cn + 1]       = acc[mi][ni][1] + b1;
            C[(size_t)(r1 + 8) * Dd + cn]     = acc[mi][ni][2] + b0;
            C[(size_t)(r1 + 8) * Dd + cn + 1] = acc[mi][ni][3] + b1;
        }
    }
}

// ---------------------------------------------------------------------------
// MMA flash attention (causal), head_dim 64, fp32 in/out.
// Block = 64-query tile of one (b,h); 4 warps; warp w owns rows [w*16,w*16+16).
// S = QK^T and O += P V on mma.m16n8k16 bf16 with hi/lo 3-term split.
// Online softmax in C-fragment registers; quad reduces via full-mask shfl
// in warp-uniform control flow.
// ---------------------------------------------------------------------------
#define VS 72   // smem stride (halves); conflict-free B-fragment reads

__global__ __launch_bounds__(128) void attn_mma_kernel(
    const float* __restrict__ Q, const float* __restrict__ K,
    const float* __restrict__ V, float* __restrict__ ctx)
{
    __shared__ __nv_bfloat16 sKh[64][VS], sKl[64][VS];   // [key][hd]
    __shared__ __nv_bfloat16 sVh[64][VS], sVl[64][VS];   // transposed [hd][key]

    int t    = threadIdx.x;
    int lane = t & 31, w = t >> 5;
    int tg   = lane & 3, gp = lane >> 2;
    int qt   = blockIdx.x;
    int bh   = blockIdx.y;
    int b    = bh >> 4, h = bh & 15;
    int q0   = qt * 64;
    int rowL0 = w * 16 + gp;            // local query rows rowL0, rowL0+8
    const float SC = 0.125f;            // 1/sqrt(64)

    // ---- load Q fragments (hi/lo), k = head dim 64 = 4 k16 steps
    uint32_t qh[4][4], ql[4][4];
    {
        const float* qb = Q + ((size_t)(b * Ss + q0 + rowL0)) * Dd + h * HDd;
        #pragma unroll
        for (int s = 0; s < 4; s++) {
            int kc = s * 16 + tg * 2;
            float2 v0 = *reinterpret_cast<const float2*>(qb + kc);
            float2 v1 = *reinterpret_cast<const float2*>(qb + (size_t)8 * Dd + kc);
            float2 v2 = *reinterpret_cast<const float2*>(qb + kc + 8);
            float2 v3 = *reinterpret_cast<const float2*>(qb + (size_t)8 * Dd + kc + 8);
            split2(v0.x, v0.y, qh[s][0], ql[s][0]);
            split2(v1.x, v1.y, qh[s][1], ql[s][1]);
            split2(v2.x, v2.y, qh[s][2], ql[s][2]);
            split2(v3.x, v3.y, qh[s][3], ql[s][3]);
        }
    }

    float m0 = -1e30f, m1 = -1e30f;
    float l0 = 0.f,    l1 = 0.f;
    float o[8][4] = {};

    for (int kt = 0; kt <= qt; kt++) {
        const bool diag = (kt == qt);
        // ---- stage K (hi/lo, [key][hd]) and V (hi/lo, transposed [hd][key])
        {
            const float* kb = K + ((size_t)(b * Ss + kt * 64)) * Dd + h * HDd;
            const float* vb = V + ((size_t)(b * Ss + kt * 64)) * Dd + h * HDd;
            #pragma unroll
            for (int e = 0; e < 16; e++) {
                int idx2 = (t + e * 128) * 2;
                int r = idx2 >> 6, c = idx2 & 63;
                float2 kv = *reinterpret_cast<const float2*>(kb + (size_t)r * Dd + c);
                uint32_t khi, klo;
                split2(kv.x, kv.y, khi, klo);
                *reinterpret_cast<uint32_t*>(&sKh[r][c]) = khi;
                *reinterpret_cast<uint32_t*>(&sKl[r][c]) = klo;
                float2 vv = *reinterpret_cast<const float2*>(vb + (size_t)r * Dd + c);
                __nv_bfloat16 vhx = __float2bfloat16(vv.x);
                __nv_bfloat16 vhy = __float2bfloat16(vv.y);
                sVh[c][r]     = vhx;
                sVh[c + 1][r] = vhy;
                sVl[c][r]     = __float2bfloat16(vv.x - __bfloat162float(vhx));
                sVl[c + 1][r] = __float2bfloat16(vv.y - __bfloat162float(vhy));
            }
        }
        __syncthreads();

        // ---- S = Q K^T (3-term split), fp32 fragments
        float sc[8][4];
        #pragma unroll
        for (int ni = 0; ni < 8; ni++)
            sc[ni][0] = sc[ni][1] = sc[ni][2] = sc[ni][3] = 0.f;
        #pragma unroll
        for (int s = 0; s < 4; s++) {
            int kc = s * 16 + tg * 2;
            #pragma unroll
            for (int ni = 0; ni < 8; ni++) {
                int kr = ni * 8 + gp;
                uint32_t bhf[2], blf[2];
                bhf[0] = *reinterpret_cast<const uint32_t*>(&sKh[kr][kc]);
                bhf[1] = *reinterpret_cast<const uint32_t*>(&sKh[kr][kc + 8]);
                blf[0] = *reinterpret_cast<const uint32_t*>(&sKl[kr][kc]);
                blf[1] = *reinterpret_cast<const uint32_t*>(&sKl[kr][kc + 8]);
                MMA16816(sc[ni], qh[s], bhf);
                MMA16816(sc[ni], ql[s], bhf);
                MMA16816(sc[ni], qh[s], blf);
            }
        }

        // ---- scale + causal mask + row max
        float mx0 = -1e30f, mx1 = -1e30f;
        #pragma unroll
        for (int ni = 0; ni < 8; ni++) {
            int c0 = ni * 8 + tg * 2;
            float s0 = sc[ni][0] * SC, s1 = sc[ni][1] * SC;
            float s2 = sc[ni][2] * SC, s3 = sc[ni][3] * SC;
            if (diag) {
                if (c0     > rowL0)     s0 = -1e30f;
                if (c0 + 1 > rowL0)     s1 = -1e30f;
                if (c0     > rowL0 + 8) s2 = -1e30f;
                if (c0 + 1 > rowL0 + 8) s3 = -1e30f;
            }
            sc[ni][0] = s0; sc[ni][1] = s1; sc[ni][2] = s2; sc[ni][3] = s3;
            mx0 = fmaxf(mx0, fmaxf(s0, s1));
            mx1 = fmaxf(mx1, fmaxf(s2, s3));
        }
        mx0 = fmaxf(mx0, __shfl_xor_sync(0xffffffffu, mx0, 1));
        mx0 = fmaxf(mx0, __shfl_xor_sync(0xffffffffu, mx0, 2));
        mx1 = fmaxf(mx1, __shfl_xor_sync(0xffffffffu, mx1, 1));
        mx1 = fmaxf(mx1, __shfl_xor_sync(0xffffffffu, mx1, 2));

        float mn0 = fmaxf(m0, mx0), mn1 = fmaxf(m1, mx1);
        float a0 = __expf(m0 - mn0), a1 = __expf(m1 - mn1);
        m0 = mn0; m1 = mn1;
        l0 *= a0; l1 *= a1;
        #pragma unroll
        for (int ni = 0; ni < 8; ni++) {
            o[ni][0] *= a0; o[ni][1] *= a0;
            o[ni][2] *= a1; o[ni][3] *= a1;
        }

        // ---- P = exp(S - m), accumulate partial row sums
        #pragma unroll
        for (int ni = 0; ni < 8; ni++) {
            float p0 = __expf(sc[ni][0] - m0);
            float p1 = __expf(sc[ni][1] - m0);
            float p2 = __expf(sc[ni][2] - m1);
            float p3 = __expf(sc[ni][3] - m1);
            l0 += p0 + p1; l1 += p2 + p3;
            sc[ni][0] = p0; sc[ni][1] = p1; sc[ni][2] = p2; sc[ni][3] = p3;
        }

        // ---- O += P V (3-term split); P C-frags repacked as A-frags
        #pragma unroll
        for (int s = 0; s < 4; s++) {
            uint32_t pah[4], pal[4];
            split2(sc[2*s][0],     sc[2*s][1],     pah[0], pal[0]);
            split2(sc[2*s][2],     sc[2*s][3],     pah[1], pal[1]);
            split2(sc[2*s + 1][0], sc[2*s + 1][1], pah[2], pal[2]);
            split2(sc[2*s + 1][2], sc[2*s + 1][3], pah[3], pal[3]);
            int kc = s * 16 + tg * 2;
            #pragma unroll
            for (int ni = 0; ni < 8; ni++) {
                int hr = ni * 8 + gp;
                uint32_t vbh[2], vbl[2];
                vbh[0] = *reinterpret_cast<const uint32_t*>(&sVh[hr][kc]);
                vbh[1] = *reinterpret_cast<const uint32_t*>(&sVh[hr][kc + 8]);
                vbl[0] = *reinterpret_cast<const uint32_t*>(&sVl[hr][kc]);
                vbl[1] = *reinterpret_cast<const uint32_t*>(&sVl[hr][kc + 8]);
                MMA16816(o[ni], pah, vbh);
                MMA16816(o[ni], pal, vbh);
                MMA16816(o[ni], pah, vbl);
            }
        }
        __syncthreads();
    }

    // ---- finalize: total row sums, normalize, write fp32 ctx
    l0 += __shfl_xor_sync(0xffffffffu, l0, 1);
    l0 += __shfl_xor_sync(0xffffffffu, l0, 2);
    l1 += __shfl_xor_sync(0xffffffffu, l1, 1);
    l1 += __shfl_xor_sync(0xffffffffu, l1, 2);
    float inv0 = 1.f / l0, inv1 = 1.f / l1;

    float* ob = ctx + ((size_t)(b * Ss + q0 + rowL0)) * Dd + h * HDd;
    #pragma unroll
    for (int ni = 0; ni < 8; ni++) {
        int c = ni * 8 + tg * 2;
        ob[c]                    = o[ni][0] * inv0;
        ob[c + 1]                = o[ni][1] * inv0;
        ob[(size_t)8 * Dd + c]     = o[ni][2] * inv1;
        ob[(size_t)8 * Dd + c + 1] = o[ni][3] * inv1;
    }
}

// ---------------------------------------------------------------------------
extern "C" void kernel_launch(void* const* d_in, const int* in_sizes, int n_in,
                              void* d_out, int out_size)
{
    const float* x  = (const float*)d_in[0];
    const float* Wq = (const float*)d_in[1];
    const float* Wk = (const float*)d_in[2];
    const float* Wv = (const float*)d_in[3];
    const float* Wo = (const float*)d_in[4];
    const float* bo = (const float*)d_in[5];
    float* out = (float*)d_out;

    float *Qp, *Kp, *Vp, *Cp;
    __nv_bfloat16 *ah, *al, *wh, *wl;
    cudaGetSymbolAddress((void**)&Qp, g_Q);
    cudaGetSymbolAddress((void**)&Kp, g_K);
    cudaGetSymbolAddress((void**)&Vp, g_V);
    cudaGetSymbolAddress((void**)&Cp, g_C);
    cudaGetSymbolAddress((void**)&ah, g_ah);
    cudaGetSymbolAddress((void**)&al, g_al);
    cudaGetSymbolAddress((void**)&wh, g_wh);
    cudaGetSymbolAddress((void**)&wl, g_wl);

    const int NX = Mrows * Dd;
    const int NW = Dd * Dd;
    dim3 gg(Dd / 64, Mrows / 128);

    split_kernel<<<NX / 256, 256>>>(x, ah, al, NX);

    split_kernel<<<NW / 256, 256>>>(Wq, wh, wl, NW);
    gemm_bf16_kernel<<<gg, 256>>>(ah, al, wh, wl, nullptr, Qp);
    split_kernel<<<NW / 256, 256>>>(Wk, wh, wl, NW);
    gemm_bf16_kernel<<<gg, 256>>>(ah, al, wh, wl, nullptr, Kp);
    split_kernel<<<NW / 256, 256>>>(Wv, wh, wl, NW);
    gemm_bf16_kernel<<<gg, 256>>>(ah, al, wh, wl, nullptr, Vp);

    attn_mma_kernel<<<dim3(Ss / 64, Bb * Hh), 128>>>(Qp, Kp, Vp, Cp);

    split_kernel<<<NX / 256, 256>>>(Cp, ah, al, NX);
    split_kernel<<<NW / 256, 256>>>(Wo, wh, wl, NW);
    gemm_bf16_kernel<<<gg, 256>>>(ah, al, wh, wl, bo, out);
}

// round 7
// speedup vs baseline: 5.1309x; 1.6394x over previous
#include <cuda_runtime.h>
#include <cuda_bf16.h>
#include <cstdint>

#define Bb 4
#define Ss 2048
#define Dd 1024
#define Hh 16
#define HDd 64
#define Mrows (Bb*Ss)   // 8192

// ---------------- scratch (device globals; no runtime allocation) ----------
__device__ __nv_bfloat16 g_ah[Mrows*Dd];   // x-split hi, later ctx-split hi
__device__ __nv_bfloat16 g_al[Mrows*Dd];
__device__ __nv_bfloat16 g_qh[Mrows*Dd], g_ql[Mrows*Dd];
__device__ __nv_bfloat16 g_kh[Mrows*Dd], g_kl[Mrows*Dd];
__device__ __nv_bfloat16 g_vh[Mrows*Dd], g_vl[Mrows*Dd];   // V^T: [b,h,d,s]
__device__ __nv_bfloat16 g_wth[4*Dd*Dd], g_wtl[4*Dd*Dd];   // W^T [w][n][k]

#define MMA16816(Cf, Af, Bf) \
    asm volatile("mma.sync.aligned.m16n8k16.row.col.f32.bf16.bf16.f32 " \
        "{%0,%1,%2,%3}, {%4,%5,%6,%7}, {%8,%9}, {%0,%1,%2,%3};" \
        : "+f"(Cf[0]), "+f"(Cf[1]), "+f"(Cf[2]), "+f"(Cf[3]) \
        : "r"(Af[0]), "r"(Af[1]), "r"(Af[2]), "r"(Af[3]), \
          "r"(Bf[0]), "r"(Bf[1]))

__device__ __forceinline__ void split2(float x, float y, uint32_t& hi, uint32_t& lo)
{
    __nv_bfloat16 hx = __float2bfloat16(x), hy = __float2bfloat16(y);
    float rx = x - __bfloat162float(hx);
    float ry = y - __bfloat162float(hy);
    __nv_bfloat162 h2(hx, hy);
    __nv_bfloat162 l2(__float2bfloat16(rx), __float2bfloat16(ry));
    hi = *reinterpret_cast<uint32_t*>(&h2);
    lo = *reinterpret_cast<uint32_t*>(&l2);
}

__device__ __forceinline__ uint32_t smaddr(const void* p) {
    uint32_t a;
    asm("{ .reg .u64 t; cvta.to.shared.u64 t, %1; cvt.u32.u64 %0, t; }"
        : "=r"(a) : "l"(p));
    return a;
}
__device__ __forceinline__ void cpa16(uint32_t dst, const void* src) {
    asm volatile("cp.async.ca.shared.global [%0], [%1], 16;" :: "r"(dst), "l"(src));
}
#define CP_COMMIT() asm volatile("cp.async.commit_group;")
#define CP_WAIT(n)  asm volatile("cp.async.wait_group %0;" :: "n"(n))

// ---------------------------------------------------------------------------
// split fp32 -> bf16 hi/lo (flat; used for x)
// ---------------------------------------------------------------------------
__global__ __launch_bounds__(256) void split_kernel(
    const float* __restrict__ in, __nv_bfloat16* __restrict__ hi,
    __nv_bfloat16* __restrict__ lo, int n)
{
    int i = blockIdx.x * 256 + threadIdx.x;
    if (i < n) {
        float x = in[i];
        __nv_bfloat16 h = __float2bfloat16(x);
        hi[i] = h;
        lo[i] = __float2bfloat16(x - __bfloat162float(h));
    }
}

// ---------------------------------------------------------------------------
// split + transpose all 4 weights: W[k][n] fp32 -> Wt[w][n][k] bf16 hi/lo
// grid (32,32,4), block (32,8)
// ---------------------------------------------------------------------------
__global__ __launch_bounds__(256) void splitW_kernel(
    const float* __restrict__ W0, const float* __restrict__ W1,
    const float* __restrict__ W2, const float* __restrict__ W3,
    __nv_bfloat16* __restrict__ th, __nv_bfloat16* __restrict__ tl)
{
    __shared__ float tile[32][33];
    int w = blockIdx.z;
    const float* W = (w == 0) ? W0 : (w == 1) ? W1 : (w == 2) ? W2 : W3;
    int bx = blockIdx.x * 32;   // n block
    int by = blockIdx.y * 32;   // k block
    int tx = threadIdx.x, ty0 = threadIdx.y;

    #pragma unroll
    for (int j = 0; j < 4; j++) {
        int k = by + ty0 + j * 8;
        tile[ty0 + j * 8][tx] = W[(size_t)k * Dd + bx + tx];
    }
    __syncthreads();
    size_t base = (size_t)w * Dd * Dd;
    #pragma unroll
    for (int j = 0; j < 4; j++) {
        int n = bx + ty0 + j * 8;
        float v = tile[tx][ty0 + j * 8];
        __nv_bfloat16 h = __float2bfloat16(v);
        th[base + (size_t)n * Dd + by + tx] = h;
        tl[base + (size_t)n * Dd + by + tx] = __float2bfloat16(v - __bfloat162float(h));
    }
}

// ---------------------------------------------------------------------------
// Tensor-core split GEMM with cp.async 2-stage pipeline.
// Block tile 128x64, K-tile 32, 256 threads (8 warps 4x2), warp tile 32x32.
// MODE 0: z in {0,1,2} selects weight + split-bf16 output (Q,K flat; V transposed)
// MODE 1: weight 3 (Wo), fp32 output + bias
// Dynamic smem layout (halves, stride GS=56):
//   A: [hl][stage][128][56]  W: base 28672 + [hl][stage][64][56]
// ---------------------------------------------------------------------------
#define GS 56
#define SM_A(hl, st)  ((hl)*14336 + (st)*7168)
#define SM_W(hl, st)  (28672 + (hl)*7168 + (st)*3584)
#define GSM_BYTES 86016

extern __shared__ __nv_bfloat16 dynsm[];

template<int MODE>
__global__ __launch_bounds__(256) void gemm_tc(
    const __nv_bfloat16* __restrict__ Ah, const __nv_bfloat16* __restrict__ Al,
    const __nv_bfloat16* __restrict__ Wth, const __nv_bfloat16* __restrict__ Wtl,
    const float* __restrict__ bias, float* __restrict__ outF,
    __nv_bfloat16* __restrict__ oqh, __nv_bfloat16* __restrict__ oql,
    __nv_bfloat16* __restrict__ okh, __nv_bfloat16* __restrict__ okl,
    __nv_bfloat16* __restrict__ ovh, __nv_bfloat16* __restrict__ ovl)
{
    int t    = threadIdx.x;
    int lane = t & 31, wid = t >> 5;
    int wm   = wid >> 1, wn = wid & 1;
    int m0   = blockIdx.y * 128, n0 = blockIdx.x * 64;
    int tg   = lane & 3, gp = lane >> 2;
    int z    = (MODE == 0) ? blockIdx.z : 3;
    size_t wbase = (size_t)z * Dd * Dd;

    uint32_t smb = smaddr(dynsm);

    // ---- async stage loader: 1536 x 16B chunks (A 1024, W 512), 6/thread
    auto stage_load = [&](int st, int k0) {
        #pragma unroll
        for (int e = 0; e < 6; e++) {
            int id = t + e * 256;
            uint32_t dst;
            const __nv_bfloat16* src;
            if (id < 1024) {
                int hl = id >> 9, rem = id & 511, r = rem >> 2, c = rem & 3;
                src = (hl ? Al : Ah) + (size_t)(m0 + r) * Dd + k0 + c * 8;
                dst = smb + 2 * (SM_A(hl, st) + r * GS + c * 8);
            } else {
                int id2 = id - 1024;
                int hl = id2 >> 8, rem = id2 & 255, r = rem >> 2, c = rem & 3;
                src = (hl ? Wtl : Wth) + wbase + (size_t)(n0 + r) * Dd + k0 + c * 8;
                dst = smb + 2 * (SM_W(hl, st) + r * GS + c * 8);
            }
            cpa16(dst, src);
        }
        CP_COMMIT();
    };

    float acc[2][4][4] = {};

    stage_load(0, 0);
    for (int it = 0; it < 32; it++) {
        int cur = it & 1;
        if (it < 31) { stage_load(cur ^ 1, (it + 1) * 32); CP_WAIT(1); }
        else         { CP_WAIT(0); }
        __syncthreads();

        const __nv_bfloat16* pAh = dynsm + SM_A(0, cur);
        const __nv_bfloat16* pAl = dynsm + SM_A(1, cur);
        const __nv_bfloat16* pWh = dynsm + SM_W(0, cur);
        const __nv_bfloat16* pWl = dynsm + SM_W(1, cur);

        #pragma unroll
        for (int kh = 0; kh < 2; kh++) {
            int kc = kh * 16 + tg * 2;
            uint32_t fah[2][4], fal[2][4];
            #pragma unroll
            for (int mi = 0; mi < 2; mi++) {
                int r1 = wm * 32 + mi * 16 + gp;
                fah[mi][0] = *(const uint32_t*)&pAh[r1 * GS + kc];
                fah[mi][1] = *(const uint32_t*)&pAh[(r1 + 8) * GS + kc];
                fah[mi][2] = *(const uint32_t*)&pAh[r1 * GS + kc + 8];
                fah[mi][3] = *(const uint32_t*)&pAh[(r1 + 8) * GS + kc + 8];
                fal[mi][0] = *(const uint32_t*)&pAl[r1 * GS + kc];
                fal[mi][1] = *(const uint32_t*)&pAl[(r1 + 8) * GS + kc];
                fal[mi][2] = *(const uint32_t*)&pAl[r1 * GS + kc + 8];
                fal[mi][3] = *(const uint32_t*)&pAl[(r1 + 8) * GS + kc + 8];
            }
            uint32_t fbh[4][2], fbl[4][2];
            #pragma unroll
            for (int ni = 0; ni < 4; ni++) {
                int cn = wn * 32 + ni * 8 + gp;
                fbh[ni][0] = *(const uint32_t*)&pWh[cn * GS + kc];
                fbh[ni][1] = *(const uint32_t*)&pWh[cn * GS + kc + 8];
                fbl[ni][0] = *(const uint32_t*)&pWl[cn * GS + kc];
                fbl[ni][1] = *(const uint32_t*)&pWl[cn * GS + kc + 8];
            }
            #pragma unroll
            for (int mi = 0; mi < 2; mi++)
                #pragma unroll
                for (int ni = 0; ni < 4; ni++) {
                    MMA16816(acc[mi][ni], fah[mi], fbh[ni]);
                    MMA16816(acc[mi][ni], fah[mi], fbl[ni]);
                    MMA16816(acc[mi][ni], fal[mi], fbh[ni]);
                }
        }
        __syncthreads();
    }

    // ---- epilogue
    #pragma unroll
    for (int mi = 0; mi < 2; mi++) {
        int r1 = m0 + wm * 32 + mi * 16 + gp;
        #pragma unroll
        for (int ni = 0; ni < 4; ni++) {
            int cn = n0 + wn * 32 + ni * 8 + tg * 2;
            if (MODE == 1) {
                float b0 = bias[cn], b1 = bias[cn + 1];
                outF[(size_t)r1 * Dd + cn]           = acc[mi][ni][0] + b0;
                outF[(size_t)r1 * Dd + cn + 1]       = acc[mi][ni][1] + b1;
                outF[(size_t)(r1 + 8) * Dd + cn]     = acc[mi][ni][2] + b0;
                outF[(size_t)(r1 + 8) * Dd + cn + 1] = acc[mi][ni][3] + b1;
            } else if (z < 2) {
                __nv_bfloat16* oh = z ? okh : oqh;
                __nv_bfloat16* ol = z ? okl : oql;
                uint32_t hw, lw;
                split2(acc[mi][ni][0], acc[mi][ni][1], hw, lw);
                *(uint32_t*)&oh[(size_t)r1 * Dd + cn] = hw;
                *(uint32_t*)&ol[(size_t)r1 * Dd + cn] = lw;
                split2(acc[mi][ni][2], acc[mi][ni][3], hw, lw);
                *(uint32_t*)&oh[(size_t)(r1 + 8) * Dd + cn] = hw;
                *(uint32_t*)&ol[(size_t)(r1 + 8) * Dd + cn] = lw;
            } else {
                // V transposed: out[((b*16+h)*64 + d)][s], m=(b,s), n=(h,d)
                #pragma unroll
                for (int rr = 0; rr < 2; rr++) {
                    int m = r1 + rr * 8;
                    int bI = m >> 11, s = m & 2047;
                    #pragma unroll
                    for (int cc = 0; cc < 2; cc++) {
                        int n = cn + cc;
                        int hI = n >> 6, d = n & 63;
                        size_t idx = ((size_t)(bI * Hh + hI) * HDd + d) * Ss + s;
                        float v = acc[mi][ni][rr * 2 + cc];
                        __nv_bfloat16 hb = __float2bfloat16(v);
                        ovh[idx] = hb;
                        ovl[idx] = __float2bfloat16(v - __bfloat162float(hb));
                    }
                }
            }
        }
    }
}

// ---------------------------------------------------------------------------
// MMA flash attention (causal), pre-split bf16 inputs, split bf16 ctx output.
// Block = 64-query tile of one (b,h); 4 warps. Same fragment algebra as R6.
// ---------------------------------------------------------------------------
#define VS 72

__global__ __launch_bounds__(128) void attn_mma_kernel(
    const __nv_bfloat16* __restrict__ Qh, const __nv_bfloat16* __restrict__ Ql,
    const __nv_bfloat16* __restrict__ Kh, const __nv_bfloat16* __restrict__ Kl,
    const __nv_bfloat16* __restrict__ Vth, const __nv_bfloat16* __restrict__ Vtl,
    __nv_bfloat16* __restrict__ Ch, __nv_bfloat16* __restrict__ Cl)
{
    __shared__ __nv_bfloat16 sKh[64][VS], sKl[64][VS];   // [key][hd]
    __shared__ __nv_bfloat16 sVh[64][VS], sVl[64][VS];   // [hd][key]

    int t    = threadIdx.x;
    int lane = t & 31, w = t >> 5;
    int tg   = lane & 3, gp = lane >> 2;
    int qt   = blockIdx.x;
    int bh   = blockIdx.y;
    int b    = bh >> 4, h = bh & 15;
    int q0   = qt * 64;
    int rowL0 = w * 16 + gp;
    const float SC = 0.125f;

    // ---- Q fragments straight from pre-split global
    uint32_t qhf[4][4], qlf[4][4];
    {
        const __nv_bfloat16* qbh = Qh + ((size_t)(b * Ss + q0 + rowL0)) * Dd + h * HDd;
        const __nv_bfloat16* qbl = Ql + ((size_t)(b * Ss + q0 + rowL0)) * Dd + h * HDd;
        #pragma unroll
        for (int s = 0; s < 4; s++) {
            int kc = s * 16 + tg * 2;
            qhf[s][0] = *(const uint32_t*)&qbh[kc];
            qhf[s][1] = *(const uint32_t*)&qbh[(size_t)8 * Dd + kc];
            qhf[s][2] = *(const uint32_t*)&qbh[kc + 8];
            qhf[s][3] = *(const uint32_t*)&qbh[(size_t)8 * Dd + kc + 8];
            qlf[s][0] = *(const uint32_t*)&qbl[kc];
            qlf[s][1] = *(const uint32_t*)&qbl[(size_t)8 * Dd + kc];
            qlf[s][2] = *(const uint32_t*)&qbl[kc + 8];
            qlf[s][3] = *(const uint32_t*)&qbl[(size_t)8 * Dd + kc + 8];
        }
    }

    float m0 = -1e30f, m1 = -1e30f;
    float l0 = 0.f,    l1 = 0.f;
    float o[8][4] = {};

    for (int kt = 0; kt <= qt; kt++) {
        const bool diag = (kt == qt);
        // ---- pure 16B-copy staging: 4 arrays x 64 rows x 8 chunks = 2048
        {
            const __nv_bfloat16* kbh = Kh + ((size_t)(b * Ss + kt * 64)) * Dd + h * HDd;
            const __nv_bfloat16* kbl = Kl + ((size_t)(b * Ss + kt * 64)) * Dd + h * HDd;
            const __nv_bfloat16* vbh = Vth + ((size_t)(b * Hh + h) * HDd) * Ss + kt * 64;
            const __nv_bfloat16* vbl = Vtl + ((size_t)(b * Hh + h) * HDd) * Ss + kt * 64;
            #pragma unroll
            for (int e = 0; e < 16; e++) {
                int id = t + e * 128;
                int arr = id >> 9, rem = id & 511, r = rem >> 3, c = rem & 7;
                const __nv_bfloat16* src =
                    (arr == 0) ? kbh + (size_t)r * Dd :
                    (arr == 1) ? kbl + (size_t)r * Dd :
                    (arr == 2) ? vbh + (size_t)r * Ss :
                                 vbl + (size_t)r * Ss;
                uint4 val = *(const uint4*)(src + c * 8);
                __nv_bfloat16* dst =
                    (arr == 0) ? &sKh[r][0] : (arr == 1) ? &sKl[r][0] :
                    (arr == 2) ? &sVh[r][0] : &sVl[r][0];
                *(uint4*)(dst + c * 8) = val;
            }
        }
        __syncthreads();

        // ---- S = Q K^T (3-term split)
        float sc[8][4];
        #pragma unroll
        for (int ni = 0; ni < 8; ni++)
            sc[ni][0] = sc[ni][1] = sc[ni][2] = sc[ni][3] = 0.f;
        #pragma unroll
        for (int s = 0; s < 4; s++) {
            int kc = s * 16 + tg * 2;
            #pragma unroll
            for (int ni = 0; ni < 8; ni++) {
                int kr = ni * 8 + gp;
                uint32_t bhf[2], blf[2];
                bhf[0] = *(const uint32_t*)&sKh[kr][kc];
                bhf[1] = *(const uint32_t*)&sKh[kr][kc + 8];
                blf[0] = *(const uint32_t*)&sKl[kr][kc];
                blf[1] = *(const uint32_t*)&sKl[kr][kc + 8];
                MMA16816(sc[ni], qhf[s], bhf);
                MMA16816(sc[ni], qlf[s], bhf);
                MMA16816(sc[ni], qhf[s], blf);
            }
        }

        // ---- scale + mask + row max
        float mx0 = -1e30f, mx1 = -1e30f;
        #pragma unroll
        for (int ni = 0; ni < 8; ni++) {
            int c0 = ni * 8 + tg * 2;
            float s0 = sc[ni][0] * SC, s1 = sc[ni][1] * SC;
            float s2 = sc[ni][2] * SC, s3 = sc[ni][3] * SC;
            if (diag) {
                if (c0     > rowL0)     s0 = -1e30f;
                if (c0 + 1 > rowL0)     s1 = -1e30f;
                if (c0     > rowL0 + 8) s2 = -1e30f;
                if (c0 + 1 > rowL0 + 8) s3 = -1e30f;
            }
            sc[ni][0] = s0; sc[ni][1] = s1; sc[ni][2] = s2; sc[ni][3] = s3;
            mx0 = fmaxf(mx0, fmaxf(s0, s1));
            mx1 = fmaxf(mx1, fmaxf(s2, s3));
        }
        mx0 = fmaxf(mx0, __shfl_xor_sync(0xffffffffu, mx0, 1));
        mx0 = fmaxf(mx0, __shfl_xor_sync(0xffffffffu, mx0, 2));
        mx1 = fmaxf(mx1, __shfl_xor_sync(0xffffffffu, mx1, 1));
        mx1 = fmaxf(mx1, __shfl_xor_sync(0xffffffffu, mx1, 2));

        float mn0 = fmaxf(m0, mx0), mn1 = fmaxf(m1, mx1);
        float a0 = __expf(m0 - mn0), a1 = __expf(m1 - mn1);
        m0 = mn0; m1 = mn1;
        l0 *= a0; l1 *= a1;
        #pragma unroll
        for (int ni = 0; ni < 8; ni++) {
            o[ni][0] *= a0; o[ni][1] *= a0;
            o[ni][2] *= a1; o[ni][3] *= a1;
        }

        // ---- P = exp(S - m)
        #pragma unroll
        for (int ni = 0; ni < 8; ni++) {
            float p0 = __expf(sc[ni][0] - m0);
            float p1 = __expf(sc[ni][1] - m0);
            float p2 = __expf(sc[ni][2] - m1);
            float p3 = __expf(sc[ni][3] - m1);
            l0 += p0 + p1; l1 += p2 + p3;
            sc[ni][0] = p0; sc[ni][1] = p1; sc[ni][2] = p2; sc[ni][3] = p3;
        }

        // ---- O += P V (3-term split)
        #pragma unroll
        for (int s = 0; s < 4; s++) {
            uint32_t pah[4], pal[4];
            split2(sc[2*s][0],     sc[2*s][1],     pah[0], pal[0]);
            split2(sc[2*s][2],     sc[2*s][3],     pah[1], pal[1]);
            split2(sc[2*s + 1][0], sc[2*s + 1][1], pah[2], pal[2]);
            split2(sc[2*s + 1][2], sc[2*s + 1][3], pah[3], pal[3]);
            int kc = s * 16 + tg * 2;
            #pragma unroll
            for (int ni = 0; ni < 8; ni++) {
                int hr = ni * 8 + gp;
                uint32_t vbh2[2], vbl2[2];
                vbh2[0] = *(const uint32_t*)&sVh[hr][kc];
                vbh2[1] = *(const uint32_t*)&sVh[hr][kc + 8];
                vbl2[0] = *(const uint32_t*)&sVl[hr][kc];
                vbl2[1] = *(const uint32_t*)&sVl[hr][kc + 8];
                MMA16816(o[ni], pah, vbh2);
                MMA16816(o[ni], pal, vbh2);
                MMA16816(o[ni], pah, vbl2);
            }
        }
        __syncthreads();
    }

    // ---- finalize + split ctx output
    l0 += __shfl_xor_sync(0xffffffffu, l0, 1);
    l0 += __shfl_xor_sync(0xffffffffu, l0, 2);
    l1 += __shfl_xor_sync(0xffffffffu, l1, 1);
    l1 += __shfl_xor_sync(0xffffffffu, l1, 2);
    float inv0 = 1.f / l0, inv1 = 1.f / l1;

    __nv_bfloat16* obh = Ch + ((size_t)(b * Ss + q0 + rowL0)) * Dd + h * HDd;
    __nv_bfloat16* obl = Cl + ((size_t)(b * Ss + q0 + rowL0)) * Dd + h * HDd;
    #pragma unroll
    for (int ni = 0; ni < 8; ni++) {
        int c = ni * 8 + tg * 2;
        uint32_t hw, lw;
        split2(o[ni][0] * inv0, o[ni][1] * inv0, hw, lw);
        *(uint32_t*)&obh[c] = hw;
        *(uint32_t*)&obl[c] = lw;
        split2(o[ni][2] * inv1, o[ni][3] * inv1, hw, lw);
        *(uint32_t*)&obh[(size_t)8 * Dd + c] = hw;
        *(uint32_t*)&obl[(size_t)8 * Dd + c] = lw;
    }
}

// ---------------------------------------------------------------------------
extern "C" void kernel_launch(void* const* d_in, const int* in_sizes, int n_in,
                              void* d_out, int out_size)
{
    const float* x  = (const float*)d_in[0];
    const float* Wq = (const float*)d_in[1];
    const float* Wk = (const float*)d_in[2];
    const float* Wv = (const float*)d_in[3];
    const float* Wo = (const float*)d_in[4];
    const float* bo = (const float*)d_in[5];
    float* out = (float*)d_out;

    __nv_bfloat16 *ah, *al, *qh, *ql, *kh, *kl, *vh, *vl, *wth, *wtl;
    cudaGetSymbolAddress((void**)&ah, g_ah);
    cudaGetSymbolAddress((void**)&al, g_al);
    cudaGetSymbolAddress((void**)&qh, g_qh);
    cudaGetSymbolAddress((void**)&ql, g_ql);
    cudaGetSymbolAddress((void**)&kh, g_kh);
    cudaGetSymbolAddress((void**)&kl, g_kl);
    cudaGetSymbolAddress((void**)&vh, g_vh);
    cudaGetSymbolAddress((void**)&vl, g_vl);
    cudaGetSymbolAddress((void**)&wth, g_wth);
    cudaGetSymbolAddress((void**)&wtl, g_wtl);

    cudaFuncSetAttribute(gemm_tc<0>, cudaFuncAttributeMaxDynamicSharedMemorySize, GSM_BYTES);
    cudaFuncSetAttribute(gemm_tc<1>, cudaFuncAttributeMaxDynamicSharedMemorySize, GSM_BYTES);

    const int NX = Mrows * Dd;

    split_kernel<<<NX / 256, 256>>>(x, ah, al, NX);
    splitW_kernel<<<dim3(32, 32, 4), dim3(32, 8)>>>(Wq, Wk, Wv, Wo, wth, wtl);

    // fused QKV projections (z selects weight/output)
    gemm_tc<0><<<dim3(16, 64, 3), 256, GSM_BYTES>>>(
        ah, al, wth, wtl, nullptr, nullptr, qh, ql, kh, kl, vh, vl);

    // attention writes split ctx into ah/al (x-split is dead now)
    attn_mma_kernel<<<dim3(Ss / 64, Bb * Hh), 128>>>(
        qh, ql, kh, kl, vh, vl, ah, al);

    // output projection
    gemm_tc<1><<<dim3(16, 64), 256, GSM_BYTES>>>(
        ah, al, wth, wtl, bo, out,
        nullptr, nullptr, nullptr, nullptr, nullptr, nullptr);
}

// round 8
// speedup vs baseline: 6.2023x; 1.2088x over previous
#include <cuda_runtime.h>
#include <cuda_bf16.h>
#include <cstdint>

#define Bb 4
#define Ss 2048
#define Dd 1024
#define Hh 16
#define HDd 64
#define Mrows (Bb*Ss)   // 8192

// ---------------- scratch (device globals; no runtime allocation) ----------
__device__ __nv_bfloat16 g_ah[Mrows*Dd];   // x-split hi, later ctx-split hi
__device__ __nv_bfloat16 g_al[Mrows*Dd];
__device__ __nv_bfloat16 g_qh[Mrows*Dd], g_ql[Mrows*Dd];
__device__ __nv_bfloat16 g_kh[Mrows*Dd], g_kl[Mrows*Dd];
__device__ __nv_bfloat16 g_vh[Mrows*Dd], g_vl[Mrows*Dd];   // V^T: [b,h,d,s]
__device__ __nv_bfloat16 g_wth[4*Dd*Dd], g_wtl[4*Dd*Dd];   // W^T [w][n][k]

#define MMA16816(Cf, Af, Bf) \
    asm volatile("mma.sync.aligned.m16n8k16.row.col.f32.bf16.bf16.f32 " \
        "{%0,%1,%2,%3}, {%4,%5,%6,%7}, {%8,%9}, {%0,%1,%2,%3};" \
        : "+f"(Cf[0]), "+f"(Cf[1]), "+f"(Cf[2]), "+f"(Cf[3]) \
        : "r"(Af[0]), "r"(Af[1]), "r"(Af[2]), "r"(Af[3]), \
          "r"(Bf[0]), "r"(Bf[1]))

// B operand given as two explicit regs
#define MMA16816R(Cf, Af, B0, B1) \
    asm volatile("mma.sync.aligned.m16n8k16.row.col.f32.bf16.bf16.f32 " \
        "{%0,%1,%2,%3}, {%4,%5,%6,%7}, {%8,%9}, {%0,%1,%2,%3};" \
        : "+f"(Cf[0]), "+f"(Cf[1]), "+f"(Cf[2]), "+f"(Cf[3]) \
        : "r"(Af[0]), "r"(Af[1]), "r"(Af[2]), "r"(Af[3]), \
          "r"(B0), "r"(B1))

#define LDSM4(r0, r1, r2, r3, addr) \
    asm volatile("ldmatrix.sync.aligned.m8n8.x4.shared.b16 {%0,%1,%2,%3}, [%4];" \
        : "=r"(r0), "=r"(r1), "=r"(r2), "=r"(r3) : "r"(addr))

__device__ __forceinline__ void split2(float x, float y, uint32_t& hi, uint32_t& lo)
{
    __nv_bfloat16 hx = __float2bfloat16(x), hy = __float2bfloat16(y);
    float rx = x - __bfloat162float(hx);
    float ry = y - __bfloat162float(hy);
    __nv_bfloat162 h2(hx, hy);
    __nv_bfloat162 l2(__float2bfloat16(rx), __float2bfloat16(ry));
    hi = *reinterpret_cast<uint32_t*>(&h2);
    lo = *reinterpret_cast<uint32_t*>(&l2);
}

__device__ __forceinline__ uint32_t smaddr(const void* p) {
    uint32_t a;
    asm("{ .reg .u64 t; cvta.to.shared.u64 t, %1; cvt.u32.u64 %0, t; }"
        : "=r"(a) : "l"(p));
    return a;
}
__device__ __forceinline__ void cpa16(uint32_t dst, const void* src) {
    asm volatile("cp.async.cg.shared.global [%0], [%1], 16;" :: "r"(dst), "l"(src));
}
#define CP_COMMIT() asm volatile("cp.async.commit_group;")
#define CP_WAIT(n)  asm volatile("cp.async.wait_group %0;" :: "n"(n))

extern __shared__ __nv_bfloat16 dynsm[];

// ---------------------------------------------------------------------------
// split fp32 -> bf16 hi/lo (flat; used for x)
// ---------------------------------------------------------------------------
__global__ __launch_bounds__(256) void split_kernel(
    const float* __restrict__ in, __nv_bfloat16* __restrict__ hi,
    __nv_bfloat16* __restrict__ lo, int n)
{
    int i = blockIdx.x * 256 + threadIdx.x;
    if (i < n) {
        float x = in[i];
        __nv_bfloat16 h = __float2bfloat16(x);
        hi[i] = h;
        lo[i] = __float2bfloat16(x - __bfloat162float(h));
    }
}

// ---------------------------------------------------------------------------
// split + transpose all 4 weights: W[k][n] fp32 -> Wt[w][n][k] bf16 hi/lo
// ---------------------------------------------------------------------------
__global__ __launch_bounds__(256) void splitW_kernel(
    const float* __restrict__ W0, const float* __restrict__ W1,
    const float* __restrict__ W2, const float* __restrict__ W3,
    __nv_bfloat16* __restrict__ th, __nv_bfloat16* __restrict__ tl)
{
    __shared__ float tile[32][33];
    int w = blockIdx.z;
    const float* W = (w == 0) ? W0 : (w == 1) ? W1 : (w == 2) ? W2 : W3;
    int bx = blockIdx.x * 32;
    int by = blockIdx.y * 32;
    int tx = threadIdx.x, ty0 = threadIdx.y;

    #pragma unroll
    for (int j = 0; j < 4; j++) {
        int k = by + ty0 + j * 8;
        tile[ty0 + j * 8][tx] = W[(size_t)k * Dd + bx + tx];
    }
    __syncthreads();
    size_t base = (size_t)w * Dd * Dd;
    #pragma unroll
    for (int j = 0; j < 4; j++) {
        int n = bx + ty0 + j * 8;
        float v = tile[tx][ty0 + j * 8];
        __nv_bfloat16 h = __float2bfloat16(v);
        th[base + (size_t)n * Dd + by + tx] = h;
        tl[base + (size_t)n * Dd + by + tx] = __float2bfloat16(v - __bfloat162float(h));
    }
}

// ---------------------------------------------------------------------------
// Tensor-core split GEMM, cp.async 2-stage pipeline + ldmatrix fragment loads.
// Block tile 128x64, K-tile 32, 256 threads (8 warps 4x2), warp tile 32x32.
// ---------------------------------------------------------------------------
#define GS 56
#define SM_A(hl, st)  ((hl)*14336 + (st)*7168)
#define SM_W(hl, st)  (28672 + (hl)*7168 + (st)*3584)
#define GSM_BYTES 86016

template<int MODE>
__global__ __launch_bounds__(256) void gemm_tc(
    const __nv_bfloat16* __restrict__ Ah, const __nv_bfloat16* __restrict__ Al,
    const __nv_bfloat16* __restrict__ Wth, const __nv_bfloat16* __restrict__ Wtl,
    const float* __restrict__ bias, float* __restrict__ outF,
    __nv_bfloat16* __restrict__ oqh, __nv_bfloat16* __restrict__ oql,
    __nv_bfloat16* __restrict__ okh, __nv_bfloat16* __restrict__ okl,
    __nv_bfloat16* __restrict__ ovh, __nv_bfloat16* __restrict__ ovl)
{
    int t    = threadIdx.x;
    int lane = t & 31, wid = t >> 5;
    int wm   = wid >> 1, wn = wid & 1;
    int m0   = blockIdx.y * 128, n0 = blockIdx.x * 64;
    int tg   = lane & 3, gp = lane >> 2;
    int z    = (MODE == 0) ? blockIdx.z : 3;
    size_t wbase = (size_t)z * Dd * Dd;

    uint32_t smb = smaddr(dynsm);

    // ldmatrix per-lane offsets
    int aRow = lane & 15, aColH = (lane >> 4) * 8;               // A: 16 rows x 2 col-halves
    int bRow = ((lane >> 4) & 1) * 8 + (lane & 7);               // B: row within 16-row pair
    int bColH = ((lane >> 3) & 1) * 8;
    int aoff = (wm * 32 + aRow) * GS + aColH;                    // + mi*16*GS + kh*16
    int boff0 = (wn * 32 + bRow) * GS + bColH;                   // + pair*16*GS + kh*16

    auto stage_load = [&](int st, int k0) {
        #pragma unroll
        for (int e = 0; e < 6; e++) {
            int id = t + e * 256;
            uint32_t dst;
            const __nv_bfloat16* src;
            if (id < 1024) {
                int hl = id >> 9, rem = id & 511, r = rem >> 2, c = rem & 3;
                src = (hl ? Al : Ah) + (size_t)(m0 + r) * Dd + k0 + c * 8;
                dst = smb + 2 * (SM_A(hl, st) + r * GS + c * 8);
            } else {
                int id2 = id - 1024;
                int hl = id2 >> 8, rem = id2 & 255, r = rem >> 2, c = rem & 3;
                src = (hl ? Wtl : Wth) + wbase + (size_t)(n0 + r) * Dd + k0 + c * 8;
                dst = smb + 2 * (SM_W(hl, st) + r * GS + c * 8);
            }
            cpa16(dst, src);
        }
        CP_COMMIT();
    };

    float acc[2][4][4] = {};

    stage_load(0, 0);
    for (int it = 0; it < 32; it++) {
        int cur = it & 1;
        if (it < 31) { stage_load(cur ^ 1, (it + 1) * 32); CP_WAIT(1); }
        else         { CP_WAIT(0); }
        __syncthreads();

        #pragma unroll
        for (int kh = 0; kh < 2; kh++) {
            uint32_t fah[2][4], fal[2][4];
            #pragma unroll
            for (int mi = 0; mi < 2; mi++) {
                uint32_t ah_ = smb + 2 * (SM_A(0, cur) + aoff + mi * 16 * GS + kh * 16);
                uint32_t al_ = smb + 2 * (SM_A(1, cur) + aoff + mi * 16 * GS + kh * 16);
                LDSM4(fah[mi][0], fah[mi][1], fah[mi][2], fah[mi][3], ah_);
                LDSM4(fal[mi][0], fal[mi][1], fal[mi][2], fal[mi][3], al_);
            }
            #pragma unroll
            for (int pair = 0; pair < 2; pair++) {
                uint32_t bh_ = smb + 2 * (SM_W(0, cur) + boff0 + pair * 16 * GS + kh * 16);
                uint32_t bl_ = smb + 2 * (SM_W(1, cur) + boff0 + pair * 16 * GS + kh * 16);
                uint32_t t0, t1, t2, t3, u0, u1, u2, u3;
                LDSM4(t0, t1, t2, t3, bh_);
                LDSM4(u0, u1, u2, u3, bl_);
                #pragma unroll
                for (int mi = 0; mi < 2; mi++) {
                    MMA16816R(acc[mi][2*pair],     fah[mi], t0, t1);
                    MMA16816R(acc[mi][2*pair],     fah[mi], u0, u1);
                    MMA16816R(acc[mi][2*pair],     fal[mi], t0, t1);
                    MMA16816R(acc[mi][2*pair + 1], fah[mi], t2, t3);
                    MMA16816R(acc[mi][2*pair + 1], fah[mi], u2, u3);
                    MMA16816R(acc[mi][2*pair + 1], fal[mi], t2, t3);
                }
            }
        }
        __syncthreads();
    }

    // ---- epilogue
    #pragma unroll
    for (int mi = 0; mi < 2; mi++) {
        int r1 = m0 + wm * 32 + mi * 16 + gp;
        #pragma unroll
        for (int ni = 0; ni < 4; ni++) {
            int cn = n0 + wn * 32 + ni * 8 + tg * 2;
            if (MODE == 1) {
                float b0 = bias[cn], b1 = bias[cn + 1];
                outF[(size_t)r1 * Dd + cn]           = acc[mi][ni][0] + b0;
                outF[(size_t)r1 * Dd + cn + 1]       = acc[mi][ni][1] + b1;
                outF[(size_t)(r1 + 8) * Dd + cn]     = acc[mi][ni][2] + b0;
                outF[(size_t)(r1 + 8) * Dd + cn + 1] = acc[mi][ni][3] + b1;
            } else if (z < 2) {
                __nv_bfloat16* oh = z ? okh : oqh;
                __nv_bfloat16* ol = z ? okl : oql;
                uint32_t hw, lw;
                split2(acc[mi][ni][0], acc[mi][ni][1], hw, lw);
                *(uint32_t*)&oh[(size_t)r1 * Dd + cn] = hw;
                *(uint32_t*)&ol[(size_t)r1 * Dd + cn] = lw;
                split2(acc[mi][ni][2], acc[mi][ni][3], hw, lw);
                *(uint32_t*)&oh[(size_t)(r1 + 8) * Dd + cn] = hw;
                *(uint32_t*)&ol[(size_t)(r1 + 8) * Dd + cn] = lw;
            } else {
                #pragma unroll
                for (int rr = 0; rr < 2; rr++) {
                    int m = r1 + rr * 8;
                    int bI = m >> 11, s = m & 2047;
                    #pragma unroll
                    for (int cc = 0; cc < 2; cc++) {
                        int n = cn + cc;
                        int hI = n >> 6, d = n & 63;
                        size_t idx = ((size_t)(bI * Hh + hI) * HDd + d) * Ss + s;
                        float v = acc[mi][ni][rr * 2 + cc];
                        __nv_bfloat16 hb = __float2bfloat16(v);
                        ovh[idx] = hb;
                        ovl[idx] = __float2bfloat16(v - __bfloat162float(hb));
                    }
                }
            }
        }
    }
}

// ---------------------------------------------------------------------------
// MMA flash attention (causal), pre-split bf16 inputs, split bf16 ctx out.
// cp.async double-buffered K/V staging + ldmatrix fragment loads.
// Block = 64-query tile of one (b,h); 4 warps; longest blocks scheduled first.
// Dynamic smem (halves): stage st: Kh,Kl,Vh,Vl each [64][72] -> 73728 B total.
// ---------------------------------------------------------------------------
#define VS 72
#define AT_OFF(arr, st) ((st) * 18432 + (arr) * 4608)

__global__ __launch_bounds__(128) void attn_mma_kernel(
    const __nv_bfloat16* __restrict__ Qh, const __nv_bfloat16* __restrict__ Ql,
    const __nv_bfloat16* __restrict__ Kh, const __nv_bfloat16* __restrict__ Kl,
    const __nv_bfloat16* __restrict__ Vth, const __nv_bfloat16* __restrict__ Vtl,
    __nv_bfloat16* __restrict__ Ch, __nv_bfloat16* __restrict__ Cl)
{
    int t    = threadIdx.x;
    int lane = t & 31, w = t >> 5;
    int tg   = lane & 3, gp = lane >> 2;
    int qt   = (int)gridDim.x - 1 - (int)blockIdx.x;   // longest first
    int bh   = blockIdx.y;
    int b    = bh >> 4, h = bh & 15;
    int q0   = qt * 64;
    int rowL0 = w * 16 + gp;
    const float SC = 0.125f;

    uint32_t smb = smaddr(dynsm);
    // ldmatrix per-lane offsets (B-operand pattern, stride VS)
    int bRow = ((lane >> 4) & 1) * 8 + (lane & 7);
    int bColH = ((lane >> 3) & 1) * 8;

    const __nv_bfloat16* kbh0 = Kh + ((size_t)(b * Ss)) * Dd + h * HDd;
    const __nv_bfloat16* kbl0 = Kl + ((size_t)(b * Ss)) * Dd + h * HDd;
    const __nv_bfloat16* vbh0 = Vth + ((size_t)(b * Hh + h) * HDd) * Ss;
    const __nv_bfloat16* vbl0 = Vtl + ((size_t)(b * Hh + h) * HDd) * Ss;

    auto stage = [&](int kt, int st) {
        #pragma unroll
        for (int e = 0; e < 16; e++) {
            int id = t + e * 128;
            int arr = id >> 9, rem = id & 511, r = rem >> 3, c = rem & 7;
            const __nv_bfloat16* src =
                (arr == 0) ? kbh0 + (size_t)(kt * 64 + r) * Dd + c * 8 :
                (arr == 1) ? kbl0 + (size_t)(kt * 64 + r) * Dd + c * 8 :
                (arr == 2) ? vbh0 + (size_t)r * Ss + kt * 64 + c * 8 :
                             vbl0 + (size_t)r * Ss + kt * 64 + c * 8;
            cpa16(smb + 2 * (AT_OFF(arr, st) + r * VS + c * 8), src);
        }
        CP_COMMIT();
    };

    // ---- Q fragments from pre-split global
    uint32_t qhf[4][4], qlf[4][4];
    {
        const __nv_bfloat16* qbh = Qh + ((size_t)(b * Ss + q0 + rowL0)) * Dd + h * HDd;
        const __nv_bfloat16* qbl = Ql + ((size_t)(b * Ss + q0 + rowL0)) * Dd + h * HDd;
        #pragma unroll
        for (int s = 0; s < 4; s++) {
            int kc = s * 16 + tg * 2;
            qhf[s][0] = *(const uint32_t*)&qbh[kc];
            qhf[s][1] = *(const uint32_t*)&qbh[(size_t)8 * Dd + kc];
            qhf[s][2] = *(const uint32_t*)&qbh[kc + 8];
            qhf[s][3] = *(const uint32_t*)&qbh[(size_t)8 * Dd + kc + 8];
            qlf[s][0] = *(const uint32_t*)&qbl[kc];
            qlf[s][1] = *(const uint32_t*)&qbl[(size_t)8 * Dd + kc];
            qlf[s][2] = *(const uint32_t*)&qbl[kc + 8];
            qlf[s][3] = *(const uint32_t*)&qbl[(size_t)8 * Dd + kc + 8];
        }
    }

    float m0 = -1e30f, m1 = -1e30f;
    float l0 = 0.f,    l1 = 0.f;
    float o[8][4] = {};

    stage(0, 0);
    for (int kt = 0; kt <= qt; kt++) {
        const bool diag = (kt == qt);
        const int st = kt & 1;
        if (kt < qt) { stage(kt + 1, st ^ 1); CP_WAIT(1); }
        else         { CP_WAIT(0); }
        __syncthreads();

        // ---- S = Q K^T (3-term split) via ldmatrix
        float sc[8][4];
        #pragma unroll
        for (int ni = 0; ni < 8; ni++)
            sc[ni][0] = sc[ni][1] = sc[ni][2] = sc[ni][3] = 0.f;
        #pragma unroll
        for (int s = 0; s < 4; s++) {
            #pragma unroll
            for (int p = 0; p < 4; p++) {
                uint32_t kh_ = smb + 2 * (AT_OFF(0, st) + (p * 16 + bRow) * VS + s * 16 + bColH);
                uint32_t kl_ = smb + 2 * (AT_OFF(1, st) + (p * 16 + bRow) * VS + s * 16 + bColH);
                uint32_t t0, t1, t2, t3, u0, u1, u2, u3;
                LDSM4(t0, t1, t2, t3, kh_);
                LDSM4(u0, u1, u2, u3, kl_);
                MMA16816R(sc[2*p],     qhf[s], t0, t1);
                MMA16816R(sc[2*p],     qlf[s], t0, t1);
                MMA16816R(sc[2*p],     qhf[s], u0, u1);
                MMA16816R(sc[2*p + 1], qhf[s], t2, t3);
                MMA16816R(sc[2*p + 1], qlf[s], t2, t3);
                MMA16816R(sc[2*p + 1], qhf[s], u2, u3);
            }
        }

        // ---- scale + mask + row max
        float mx0 = -1e30f, mx1 = -1e30f;
        #pragma unroll
        for (int ni = 0; ni < 8; ni++) {
            int c0 = ni * 8 + tg * 2;
            float s0 = sc[ni][0] * SC, s1 = sc[ni][1] * SC;
            float s2 = sc[ni][2] * SC, s3 = sc[ni][3] * SC;
            if (diag) {
                if (c0     > rowL0)     s0 = -1e30f;
                if (c0 + 1 > rowL0)     s1 = -1e30f;
                if (c0     > rowL0 + 8) s2 = -1e30f;
                if (c0 + 1 > rowL0 + 8) s3 = -1e30f;
            }
            sc[ni][0] = s0; sc[ni][1] = s1; sc[ni][2] = s2; sc[ni][3] = s3;
            mx0 = fmaxf(mx0, fmaxf(s0, s1));
            mx1 = fmaxf(mx1, fmaxf(s2, s3));
        }
        mx0 = fmaxf(mx0, __shfl_xor_sync(0xffffffffu, mx0, 1));
        mx0 = fmaxf(mx0, __shfl_xor_sync(0xffffffffu, mx0, 2));
        mx1 = fmaxf(mx1, __shfl_xor_sync(0xffffffffu, mx1, 1));
        mx1 = fmaxf(mx1, __shfl_xor_sync(0xffffffffu, mx1, 2));

        float mn0 = fmaxf(m0, mx0), mn1 = fmaxf(m1, mx1);
        float a0 = __expf(m0 - mn0), a1 = __expf(m1 - mn1);
        m0 = mn0; m1 = mn1;
        l0 *= a0; l1 *= a1;
        #pragma unroll
        for (int ni = 0; ni < 8; ni++) {
            o[ni][0] *= a0; o[ni][1] *= a0;
            o[ni][2] *= a1; o[ni][3] *= a1;
        }

        // ---- P = exp(S - m)
        #pragma unroll
        for (int ni = 0; ni < 8; ni++) {
            float p0 = __expf(sc[ni][0] - m0);
            float p1 = __expf(sc[ni][1] - m0);
            float p2 = __expf(sc[ni][2] - m1);
            float p3 = __expf(sc[ni][3] - m1);
            l0 += p0 + p1; l1 += p2 + p3;
            sc[ni][0] = p0; sc[ni][1] = p1; sc[ni][2] = p2; sc[ni][3] = p3;
        }

        // ---- O += P V (3-term split) via ldmatrix
        #pragma unroll
        for (int s = 0; s < 4; s++) {
            uint32_t pah[4], pal[4];
            split2(sc[2*s][0],     sc[2*s][1],     pah[0], pal[0]);
            split2(sc[2*s][2],     sc[2*s][3],     pah[1], pal[1]);
            split2(sc[2*s + 1][0], sc[2*s + 1][1], pah[2], pal[2]);
            split2(sc[2*s + 1][2], sc[2*s + 1][3], pah[3], pal[3]);
            #pragma unroll
            for (int p = 0; p < 4; p++) {
                uint32_t vh_ = smb + 2 * (AT_OFF(2, st) + (p * 16 + bRow) * VS + s * 16 + bColH);
                uint32_t vl_ = smb + 2 * (AT_OFF(3, st) + (p * 16 + bRow) * VS + s * 16 + bColH);
                uint32_t t0, t1, t2, t3, u0, u1, u2, u3;
                LDSM4(t0, t1, t2, t3, vh_);
                LDSM4(u0, u1, u2, u3, vl_);
                MMA16816R(o[2*p],     pah, t0, t1);
                MMA16816R(o[2*p],     pal, t0, t1);
                MMA16816R(o[2*p],     pah, u0, u1);
                MMA16816R(o[2*p + 1], pah, t2, t3);
                MMA16816R(o[2*p + 1], pal, t2, t3);
                MMA16816R(o[2*p + 1], pah, u2, u3);
            }
        }
        __syncthreads();
    }

    // ---- finalize + split ctx output
    l0 += __shfl_xor_sync(0xffffffffu, l0, 1);
    l0 += __shfl_xor_sync(0xffffffffu, l0, 2);
    l1 += __shfl_xor_sync(0xffffffffu, l1, 1);
    l1 += __shfl_xor_sync(0xffffffffu, l1, 2);
    float inv0 = 1.f / l0, inv1 = 1.f / l1;

    __nv_bfloat16* obh = Ch + ((size_t)(b * Ss + q0 + rowL0)) * Dd + h * HDd;
    __nv_bfloat16* obl = Cl + ((size_t)(b * Ss + q0 + rowL0)) * Dd + h * HDd;
    #pragma unroll
    for (int ni = 0; ni < 8; ni++) {
        int c = ni * 8 + tg * 2;
        uint32_t hw, lw;
        split2(o[ni][0] * inv0, o[ni][1] * inv0, hw, lw);
        *(uint32_t*)&obh[c] = hw;
        *(uint32_t*)&obl[c] = lw;
        split2(o[ni][2] * inv1, o[ni][3] * inv1, hw, lw);
        *(uint32_t*)&obh[(size_t)8 * Dd + c] = hw;
        *(uint32_t*)&obl[(size_t)8 * Dd + c] = lw;
    }
}

// ---------------------------------------------------------------------------
extern "C" void kernel_launch(void* const* d_in, const int* in_sizes, int n_in,
                              void* d_out, int out_size)
{
    const float* x  = (const float*)d_in[0];
    const float* Wq = (const float*)d_in[1];
    const float* Wk = (const float*)d_in[2];
    const float* Wv = (const float*)d_in[3];
    const float* Wo = (const float*)d_in[4];
    const float* bo = (const float*)d_in[5];
    float* out = (float*)d_out;

    __nv_bfloat16 *ah, *al, *qh, *ql, *kh, *kl, *vh, *vl, *wth, *wtl;
    cudaGetSymbolAddress((void**)&ah, g_ah);
    cudaGetSymbolAddress((void**)&al, g_al);
    cudaGetSymbolAddress((void**)&qh, g_qh);
    cudaGetSymbolAddress((void**)&ql, g_ql);
    cudaGetSymbolAddress((void**)&kh, g_kh);
    cudaGetSymbolAddress((void**)&kl, g_kl);
    cudaGetSymbolAddress((void**)&vh, g_vh);
    cudaGetSymbolAddress((void**)&vl, g_vl);
    cudaGetSymbolAddress((void**)&wth, g_wth);
    cudaGetSymbolAddress((void**)&wtl, g_wtl);

    cudaFuncSetAttribute(gemm_tc<0>, cudaFuncAttributeMaxDynamicSharedMemorySize, GSM_BYTES);
    cudaFuncSetAttribute(gemm_tc<1>, cudaFuncAttributeMaxDynamicSharedMemorySize, GSM_BYTES);
    cudaFuncSetAttribute(attn_mma_kernel, cudaFuncAttributeMaxDynamicSharedMemorySize, 73728);

    const int NX = Mrows * Dd;

    split_kernel<<<NX / 256, 256>>>(x, ah, al, NX);
    splitW_kernel<<<dim3(32, 32, 4), dim3(32, 8)>>>(Wq, Wk, Wv, Wo, wth, wtl);

    gemm_tc<0><<<dim3(16, 64, 3), 256, GSM_BYTES>>>(
        ah, al, wth, wtl, nullptr, nullptr, qh, ql, kh, kl, vh, vl);

    attn_mma_kernel<<<dim3(Ss / 64, Bb * Hh), 128, 73728>>>(
        qh, ql, kh, kl, vh, vl, ah, al);

    gemm_tc<1><<<dim3(16, 64), 256, GSM_BYTES>>>(
        ah, al, wth, wtl, bo, out,
        nullptr, nullptr, nullptr, nullptr, nullptr, nullptr);
}

// round 9
// speedup vs baseline: 6.9249x; 1.1165x over previous
#include <cuda_runtime.h>
#include <cuda_bf16.h>
#include <cstdint>

#define Bb 4
#define Ss 2048
#define Dd 1024
#define Hh 16
#define HDd 64
#define Mrows (Bb*Ss)   // 8192

// ---------------- scratch (device globals; no runtime allocation) ----------
__device__ __nv_bfloat16 g_ah[Mrows*Dd];   // x-split hi, later ctx-split hi
__device__ __nv_bfloat16 g_al[Mrows*Dd];
__device__ __nv_bfloat16 g_qh[Mrows*Dd], g_ql[Mrows*Dd];
__device__ __nv_bfloat16 g_kh[Mrows*Dd], g_kl[Mrows*Dd];
__device__ __nv_bfloat16 g_vh[Mrows*Dd], g_vl[Mrows*Dd];   // V^T: [b,h,d,s]
__device__ __nv_bfloat16 g_wth[4*Dd*Dd], g_wtl[4*Dd*Dd];   // W^T [w][n][k]

#define MMA16816R(Cf, Af, B0, B1) \
    asm volatile("mma.sync.aligned.m16n8k16.row.col.f32.bf16.bf16.f32 " \
        "{%0,%1,%2,%3}, {%4,%5,%6,%7}, {%8,%9}, {%0,%1,%2,%3};" \
        : "+f"(Cf[0]), "+f"(Cf[1]), "+f"(Cf[2]), "+f"(Cf[3]) \
        : "r"(Af[0]), "r"(Af[1]), "r"(Af[2]), "r"(Af[3]), \
          "r"(B0), "r"(B1))

#define LDSM4(r0, r1, r2, r3, addr) \
    asm volatile("ldmatrix.sync.aligned.m8n8.x4.shared.b16 {%0,%1,%2,%3}, [%4];" \
        : "=r"(r0), "=r"(r1), "=r"(r2), "=r"(r3) : "r"(addr))

__device__ __forceinline__ void split2(float x, float y, uint32_t& hi, uint32_t& lo)
{
    __nv_bfloat16 hx = __float2bfloat16(x), hy = __float2bfloat16(y);
    float rx = x - __bfloat162float(hx);
    float ry = y - __bfloat162float(hy);
    __nv_bfloat162 h2(hx, hy);
    __nv_bfloat162 l2(__float2bfloat16(rx), __float2bfloat16(ry));
    hi = *reinterpret_cast<uint32_t*>(&h2);
    lo = *reinterpret_cast<uint32_t*>(&l2);
}

__device__ __forceinline__ uint32_t smaddr(const void* p) {
    uint32_t a;
    asm("{ .reg .u64 t; cvta.to.shared.u64 t, %1; cvt.u32.u64 %0, t; }"
        : "=r"(a) : "l"(p));
    return a;
}
__device__ __forceinline__ void cpa16(uint32_t dst, const void* src) {
    asm volatile("cp.async.cg.shared.global [%0], [%1], 16;" :: "r"(dst), "l"(src));
}
#define CP_COMMIT() asm volatile("cp.async.commit_group;")
#define CP_WAIT(n)  asm volatile("cp.async.wait_group %0;" :: "n"(n))

extern __shared__ __nv_bfloat16 dynsm[];

// ---------------------------------------------------------------------------
// split fp32 -> bf16 hi/lo (flat; used for x)
// ---------------------------------------------------------------------------
__global__ __launch_bounds__(256) void split_kernel(
    const float* __restrict__ in, __nv_bfloat16* __restrict__ hi,
    __nv_bfloat16* __restrict__ lo, int n)
{
    int i = blockIdx.x * 256 + threadIdx.x;
    if (i < n) {
        float x = in[i];
        __nv_bfloat16 h = __float2bfloat16(x);
        hi[i] = h;
        lo[i] = __float2bfloat16(x - __bfloat162float(h));
    }
}

// ---------------------------------------------------------------------------
// split + transpose all 4 weights: W[k][n] fp32 -> Wt[w][n][k] bf16 hi/lo
// ---------------------------------------------------------------------------
__global__ __launch_bounds__(256) void splitW_kernel(
    const float* __restrict__ W0, const float* __restrict__ W1,
    const float* __restrict__ W2, const float* __restrict__ W3,
    __nv_bfloat16* __restrict__ th, __nv_bfloat16* __restrict__ tl)
{
    __shared__ float tile[32][33];
    int w = blockIdx.z;
    const float* W = (w == 0) ? W0 : (w == 1) ? W1 : (w == 2) ? W2 : W3;
    int bx = blockIdx.x * 32;
    int by = blockIdx.y * 32;
    int tx = threadIdx.x, ty0 = threadIdx.y;

    #pragma unroll
    for (int j = 0; j < 4; j++) {
        int k = by + ty0 + j * 8;
        tile[ty0 + j * 8][tx] = W[(size_t)k * Dd + bx + tx];
    }
    __syncthreads();
    size_t base = (size_t)w * Dd * Dd;
    #pragma unroll
    for (int j = 0; j < 4; j++) {
        int n = bx + ty0 + j * 8;
        float v = tile[tx][ty0 + j * 8];
        __nv_bfloat16 h = __float2bfloat16(v);
        th[base + (size_t)n * Dd + by + tx] = h;
        tl[base + (size_t)n * Dd + by + tx] = __float2bfloat16(v - __bfloat162float(h));
    }
}

// ---------------------------------------------------------------------------
// Tensor-core split GEMM, cp.async 2-stage pipeline, K-tile 64, ldmatrix.
// Block tile 128x64, 256 threads (8 warps 4x2), warp tile 32x32.
// smem halves, stride GS=72:
//   A[hl][st]: 128x72  -> SM_A ; W[hl][st]: 64x72 -> SM_W. Total 110592 B.
// ---------------------------------------------------------------------------
#define GS 72
#define SM_A(hl, st)  ((hl)*18432 + (st)*9216)
#define SM_W(hl, st)  (36864 + (hl)*9216 + (st)*4608)
#define GSM_BYTES 110592

template<int MODE>
__global__ __launch_bounds__(256) void gemm_tc(
    const __nv_bfloat16* __restrict__ Ah, const __nv_bfloat16* __restrict__ Al,
    const __nv_bfloat16* __restrict__ Wth, const __nv_bfloat16* __restrict__ Wtl,
    const float* __restrict__ bias, float* __restrict__ outF,
    __nv_bfloat16* __restrict__ oqh, __nv_bfloat16* __restrict__ oql,
    __nv_bfloat16* __restrict__ okh, __nv_bfloat16* __restrict__ okl,
    __nv_bfloat16* __restrict__ ovh, __nv_bfloat16* __restrict__ ovl)
{
    int t    = threadIdx.x;
    int lane = t & 31, wid = t >> 5;
    int wm   = wid >> 1, wn = wid & 1;
    int m0   = blockIdx.y * 128, n0 = blockIdx.x * 64;
    int tg   = lane & 3, gp = lane >> 2;
    int z    = (MODE == 0) ? blockIdx.z : 3;
    size_t wbase = (size_t)z * Dd * Dd;

    uint32_t smb = smaddr(dynsm);

    int aRow = lane & 15, aColH = (lane >> 4) * 8;
    int bRow = ((lane >> 4) & 1) * 8 + (lane & 7);
    int bColH = ((lane >> 3) & 1) * 8;
    int aoff = (wm * 32 + aRow) * GS + aColH;
    int boff0 = (wn * 32 + bRow) * GS + bColH;

    // stage: A 2048 chunks + W 1024 chunks of 16B => 12 per thread
    auto stage_load = [&](int st, int k0) {
        #pragma unroll
        for (int e = 0; e < 12; e++) {
            int id = t + e * 256;
            uint32_t dst;
            const __nv_bfloat16* src;
            if (id < 2048) {
                int hl = id >> 10, rem = id & 1023, r = rem >> 3, c = rem & 7;
                src = (hl ? Al : Ah) + (size_t)(m0 + r) * Dd + k0 + c * 8;
                dst = smb + 2 * (SM_A(hl, st) + r * GS + c * 8);
            } else {
                int id2 = id - 2048;
                int hl = id2 >> 9, rem = id2 & 511, r = rem >> 3, c = rem & 7;
                src = (hl ? Wtl : Wth) + wbase + (size_t)(n0 + r) * Dd + k0 + c * 8;
                dst = smb + 2 * (SM_W(hl, st) + r * GS + c * 8);
            }
            cpa16(dst, src);
        }
        CP_COMMIT();
    };

    float acc[2][4][4] = {};

    stage_load(0, 0);
    for (int it = 0; it < 16; it++) {
        int cur = it & 1;
        if (it < 15) { stage_load(cur ^ 1, (it + 1) * 64); CP_WAIT(1); }
        else         { CP_WAIT(0); }
        __syncthreads();

        #pragma unroll
        for (int kh = 0; kh < 4; kh++) {
            uint32_t fah[2][4], fal[2][4];
            #pragma unroll
            for (int mi = 0; mi < 2; mi++) {
                uint32_t ah_ = smb + 2 * (SM_A(0, cur) + aoff + mi * 16 * GS + kh * 16);
                uint32_t al_ = smb + 2 * (SM_A(1, cur) + aoff + mi * 16 * GS + kh * 16);
                LDSM4(fah[mi][0], fah[mi][1], fah[mi][2], fah[mi][3], ah_);
                LDSM4(fal[mi][0], fal[mi][1], fal[mi][2], fal[mi][3], al_);
            }
            #pragma unroll
            for (int pair = 0; pair < 2; pair++) {
                uint32_t bh_ = smb + 2 * (SM_W(0, cur) + boff0 + pair * 16 * GS + kh * 16);
                uint32_t bl_ = smb + 2 * (SM_W(1, cur) + boff0 + pair * 16 * GS + kh * 16);
                uint32_t t0, t1, t2, t3, u0, u1, u2, u3;
                LDSM4(t0, t1, t2, t3, bh_);
                LDSM4(u0, u1, u2, u3, bl_);
                #pragma unroll
                for (int mi = 0; mi < 2; mi++) {
                    MMA16816R(acc[mi][2*pair],     fah[mi], t0, t1);
                    MMA16816R(acc[mi][2*pair],     fah[mi], u0, u1);
                    MMA16816R(acc[mi][2*pair],     fal[mi], t0, t1);
                    MMA16816R(acc[mi][2*pair + 1], fah[mi], t2, t3);
                    MMA16816R(acc[mi][2*pair + 1], fah[mi], u2, u3);
                    MMA16816R(acc[mi][2*pair + 1], fal[mi], t2, t3);
                }
            }
        }
        __syncthreads();
    }

    // ---- epilogue
    #pragma unroll
    for (int mi = 0; mi < 2; mi++) {
        int r1 = m0 + wm * 32 + mi * 16 + gp;
        #pragma unroll
        for (int ni = 0; ni < 4; ni++) {
            int cn = n0 + wn * 32 + ni * 8 + tg * 2;
            if (MODE == 1) {
                float b0 = bias[cn], b1 = bias[cn + 1];
                outF[(size_t)r1 * Dd + cn]           = acc[mi][ni][0] + b0;
                outF[(size_t)r1 * Dd + cn + 1]       = acc[mi][ni][1] + b1;
                outF[(size_t)(r1 + 8) * Dd + cn]     = acc[mi][ni][2] + b0;
                outF[(size_t)(r1 + 8) * Dd + cn + 1] = acc[mi][ni][3] + b1;
            } else if (z < 2) {
                __nv_bfloat16* oh = z ? okh : oqh;
                __nv_bfloat16* ol = z ? okl : oql;
                uint32_t hw, lw;
                split2(acc[mi][ni][0], acc[mi][ni][1], hw, lw);
                *(uint32_t*)&oh[(size_t)r1 * Dd + cn] = hw;
                *(uint32_t*)&ol[(size_t)r1 * Dd + cn] = lw;
                split2(acc[mi][ni][2], acc[mi][ni][3], hw, lw);
                *(uint32_t*)&oh[(size_t)(r1 + 8) * Dd + cn] = hw;
                *(uint32_t*)&ol[(size_t)(r1 + 8) * Dd + cn] = lw;
            } else {
                #pragma unroll
                for (int rr = 0; rr < 2; rr++) {
                    int m = r1 + rr * 8;
                    int bI = m >> 11, s = m & 2047;
                    #pragma unroll
                    for (int cc = 0; cc < 2; cc++) {
                        int n = cn + cc;
                        int hI = n >> 6, d = n & 63;
                        size_t idx = ((size_t)(bI * Hh + hI) * HDd + d) * Ss + s;
                        float v = acc[mi][ni][rr * 2 + cc];
                        __nv_bfloat16 hb = __float2bfloat16(v);
                        ovh[idx] = hb;
                        ovl[idx] = __float2bfloat16(v - __bfloat162float(hb));
                    }
                }
            }
        }
    }
}

// ---------------------------------------------------------------------------
// MMA flash attention (causal). K double-buffered, V single-buffered with
// post-sync prefetch; commit-group protocol: wait_group(1) at iter top drains
// exactly K(kt)+V(kt). 4 blocks/SM (55296 B smem, <=128 regs).
// smem halves: K[hl][st]: st*9216 + hl*4608 (64x72); V[hl]: 18432 + hl*4608.
// ---------------------------------------------------------------------------
#define VS 72
#define K_OFF(hl, st) ((st) * 9216 + (hl) * 4608)
#define V_OFF(hl)     (18432 + (hl) * 4608)
#define ASM_BYTES 55296

__global__ __launch_bounds__(128, 4) void attn_mma_kernel(
    const __nv_bfloat16* __restrict__ Qh, const __nv_bfloat16* __restrict__ Ql,
    const __nv_bfloat16* __restrict__ Kh, const __nv_bfloat16* __restrict__ Kl,
    const __nv_bfloat16* __restrict__ Vth, const __nv_bfloat16* __restrict__ Vtl,
    __nv_bfloat16* __restrict__ Ch, __nv_bfloat16* __restrict__ Cl)
{
    int t    = threadIdx.x;
    int lane = t & 31, w = t >> 5;
    int tg   = lane & 3, gp = lane >> 2;
    int qt   = (int)gridDim.x - 1 - (int)blockIdx.x;   // longest first
    int bh   = blockIdx.y;
    int b    = bh >> 4, h = bh & 15;
    int q0   = qt * 64;
    int rowL0 = w * 16 + gp;
    const float SC = 0.125f;

    uint32_t smb = smaddr(dynsm);
    int bRow = ((lane >> 4) & 1) * 8 + (lane & 7);
    int bColH = ((lane >> 3) & 1) * 8;

    const __nv_bfloat16* kbh0 = Kh + ((size_t)(b * Ss)) * Dd + h * HDd;
    const __nv_bfloat16* kbl0 = Kl + ((size_t)(b * Ss)) * Dd + h * HDd;
    const __nv_bfloat16* vbh0 = Vth + ((size_t)(b * Hh + h) * HDd) * Ss;
    const __nv_bfloat16* vbl0 = Vtl + ((size_t)(b * Hh + h) * HDd) * Ss;

    // 1024 16B chunks each (2 arrays x 64 rows x 8): 8 per thread
    auto stageK = [&](int kt, int st) {
        #pragma unroll
        for (int e = 0; e < 8; e++) {
            int id = t + e * 128;
            int hl = id >> 9, rem = id & 511, r = rem >> 3, c = rem & 7;
            const __nv_bfloat16* src =
                (hl ? kbl0 : kbh0) + (size_t)(kt * 64 + r) * Dd + c * 8;
            cpa16(smb + 2 * (K_OFF(hl, st) + r * VS + c * 8), src);
        }
    };
    auto stageV = [&](int kt) {
        #pragma unroll
        for (int e = 0; e < 8; e++) {
            int id = t + e * 128;
            int hl = id >> 9, rem = id & 511, r = rem >> 3, c = rem & 7;
            const __nv_bfloat16* src =
                (hl ? vbl0 : vbh0) + (size_t)r * Ss + kt * 64 + c * 8;
            cpa16(smb + 2 * (V_OFF(hl) + r * VS + c * 8), src);
        }
    };

    // ---- Q fragments from pre-split global
    uint32_t qhf[4][4], qlf[4][4];
    {
        const __nv_bfloat16* qbh = Qh + ((size_t)(b * Ss + q0 + rowL0)) * Dd + h * HDd;
        const __nv_bfloat16* qbl = Ql + ((size_t)(b * Ss + q0 + rowL0)) * Dd + h * HDd;
        #pragma unroll
        for (int s = 0; s < 4; s++) {
            int kc = s * 16 + tg * 2;
            qhf[s][0] = *(const uint32_t*)&qbh[kc];
            qhf[s][1] = *(const uint32_t*)&qbh[(size_t)8 * Dd + kc];
            qhf[s][2] = *(const uint32_t*)&qbh[kc + 8];
            qhf[s][3] = *(const uint32_t*)&qbh[(size_t)8 * Dd + kc + 8];
            qlf[s][0] = *(const uint32_t*)&qbl[kc];
            qlf[s][1] = *(const uint32_t*)&qbl[(size_t)8 * Dd + kc];
            qlf[s][2] = *(const uint32_t*)&qbl[kc + 8];
            qlf[s][3] = *(const uint32_t*)&qbl[(size_t)8 * Dd + kc + 8];
        }
    }

    float m0 = -1e30f, m1 = -1e30f;
    float l0 = 0.f,    l1 = 0.f;
    float o[8][4] = {};

    // prologue: group{K0,V0}; group{K1 (if any)}
    stageK(0, 0);
    stageV(0);
    CP_COMMIT();
    if (1 <= qt) stageK(1, 1);
    CP_COMMIT();

    for (int kt = 0; kt <= qt; kt++) {
        const bool diag = (kt == qt);
        const int st = kt & 1;
        CP_WAIT(1);           // drains K(kt) and V(kt); leaves newest group
        __syncthreads();

        // ---- S = Q K^T (3-term split) via ldmatrix
        float sc[8][4];
        #pragma unroll
        for (int ni = 0; ni < 8; ni++)
            sc[ni][0] = sc[ni][1] = sc[ni][2] = sc[ni][3] = 0.f;
        #pragma unroll
        for (int s = 0; s < 4; s++) {
            #pragma unroll
            for (int p = 0; p < 4; p++) {
                uint32_t kh_ = smb + 2 * (K_OFF(0, st) + (p * 16 + bRow) * VS + s * 16 + bColH);
                uint32_t kl_ = smb + 2 * (K_OFF(1, st) + (p * 16 + bRow) * VS + s * 16 + bColH);
                uint32_t t0, t1, t2, t3, u0, u1, u2, u3;
                LDSM4(t0, t1, t2, t3, kh_);
                LDSM4(u0, u1, u2, u3, kl_);
                MMA16816R(sc[2*p],     qhf[s], t0, t1);
                MMA16816R(sc[2*p],     qlf[s], t0, t1);
                MMA16816R(sc[2*p],     qhf[s], u0, u1);
                MMA16816R(sc[2*p + 1], qhf[s], t2, t3);
                MMA16816R(sc[2*p + 1], qlf[s], t2, t3);
                MMA16816R(sc[2*p + 1], qhf[s], u2, u3);
            }
        }

        // ---- scale + mask + row max
        float mx0 = -1e30f, mx1 = -1e30f;
        #pragma unroll
        for (int ni = 0; ni < 8; ni++) {
            int c0 = ni * 8 + tg * 2;
            float s0 = sc[ni][0] * SC, s1 = sc[ni][1] * SC;
            float s2 = sc[ni][2] * SC, s3 = sc[ni][3] * SC;
            if (diag) {
                if (c0     > rowL0)     s0 = -1e30f;
                if (c0 + 1 > rowL0)     s1 = -1e30f;
                if (c0     > rowL0 + 8) s2 = -1e30f;
                if (c0 + 1 > rowL0 + 8) s3 = -1e30f;
            }
            sc[ni][0] = s0; sc[ni][1] = s1; sc[ni][2] = s2; sc[ni][3] = s3;
            mx0 = fmaxf(mx0, fmaxf(s0, s1));
            mx1 = fmaxf(mx1, fmaxf(s2, s3));
        }
        mx0 = fmaxf(mx0, __shfl_xor_sync(0xffffffffu, mx0, 1));
        mx0 = fmaxf(mx0, __shfl_xor_sync(0xffffffffu, mx0, 2));
        mx1 = fmaxf(mx1, __shfl_xor_sync(0xffffffffu, mx1, 1));
        mx1 = fmaxf(mx1, __shfl_xor_sync(0xffffffffu, mx1, 2));

        float mn0 = fmaxf(m0, mx0), mn1 = fmaxf(m1, mx1);
        float a0 = __expf(m0 - mn0), a1 = __expf(m1 - mn1);
        m0 = mn0; m1 = mn1;
        l0 *= a0; l1 *= a1;
        #pragma unroll
        for (int ni = 0; ni < 8; ni++) {
            o[ni][0] *= a0; o[ni][1] *= a0;
            o[ni][2] *= a1; o[ni][3] *= a1;
        }

        // ---- P = exp(S - m)
        #pragma unroll
        for (int ni = 0; ni < 8; ni++) {
            float p0 = __expf(sc[ni][0] - m0);
            float p1 = __expf(sc[ni][1] - m0);
            float p2 = __expf(sc[ni][2] - m1);
            float p3 = __expf(sc[ni][3] - m1);
            l0 += p0 + p1; l1 += p2 + p3;
            sc[ni][0] = p0; sc[ni][1] = p1; sc[ni][2] = p2; sc[ni][3] = p3;
        }

        // ---- O += P V (3-term split) via ldmatrix
        #pragma unroll
        for (int s = 0; s < 4; s++) {
            uint32_t pah[4], pal[4];
            split2(sc[2*s][0],     sc[2*s][1],     pah[0], pal[0]);
            split2(sc[2*s][2],     sc[2*s][3],     pah[1], pal[1]);
            split2(sc[2*s + 1][0], sc[2*s + 1][1], pah[2], pal[2]);
            split2(sc[2*s + 1][2], sc[2*s + 1][3], pah[3], pal[3]);
            #pragma unroll
            for (int p = 0; p < 4; p++) {
                uint32_t vh_ = smb + 2 * (V_OFF(0) + (p * 16 + bRow) * VS + s * 16 + bColH);
                uint32_t vl_ = smb + 2 * (V_OFF(1) + (p * 16 + bRow) * VS + s * 16 + bColH);
                uint32_t t0, t1, t2, t3, u0, u1, u2, u3;
                LDSM4(t0, t1, t2, t3, vh_);
                LDSM4(u0, u1, u2, u3, vl_);
                MMA16816R(o[2*p],     pah, t0, t1);
                MMA16816R(o[2*p],     pal, t0, t1);
                MMA16816R(o[2*p],     pah, u0, u1);
                MMA16816R(o[2*p + 1], pah, t2, t3);
                MMA16816R(o[2*p + 1], pal, t2, t3);
                MMA16816R(o[2*p + 1], pah, u2, u3);
            }
        }
        __syncthreads();    // everyone done with V(kt) and K(kt)

        if (kt < qt) {
            stageV(kt + 1);                    // into single V buffer (safe now)
            CP_COMMIT();
            if (kt + 2 <= qt) stageK(kt + 2, (kt + 2) & 1);
            CP_COMMIT();
        }
    }

    // ---- finalize + split ctx output
    l0 += __shfl_xor_sync(0xffffffffu, l0, 1);
    l0 += __shfl_xor_sync(0xffffffffu, l0, 2);
    l1 += __shfl_xor_sync(0xffffffffu, l1, 1);
    l1 += __shfl_xor_sync(0xffffffffu, l1, 2);
    float inv0 = 1.f / l0, inv1 = 1.f / l1;

    __nv_bfloat16* obh = Ch + ((size_t)(b * Ss + q0 + rowL0)) * Dd + h * HDd;
    __nv_bfloat16* obl = Cl + ((size_t)(b * Ss + q0 + rowL0)) * Dd + h * HDd;
    #pragma unroll
    for (int ni = 0; ni < 8; ni++) {
        int c = ni * 8 + tg * 2;
        uint32_t hw, lw;
        split2(o[ni][0] * inv0, o[ni][1] * inv0, hw, lw);
        *(uint32_t*)&obh[c] = hw;
        *(uint32_t*)&obl[c] = lw;
        split2(o[ni][2] * inv1, o[ni][3] * inv1, hw, lw);
        *(uint32_t*)&obh[(size_t)8 * Dd + c] = hw;
        *(uint32_t*)&obl[(size_t)8 * Dd + c] = lw;
    }
}

// ---------------------------------------------------------------------------
extern "C" void kernel_launch(void* const* d_in, const int* in_sizes, int n_in,
                              void* d_out, int out_size)
{
    const float* x  = (const float*)d_in[0];
    const float* Wq = (const float*)d_in[1];
    const float* Wk = (const float*)d_in[2];
    const float* Wv = (const float*)d_in[3];
    const float* Wo = (const float*)d_in[4];
    const float* bo = (const float*)d_in[5];
    float* out = (float*)d_out;

    __nv_bfloat16 *ah, *al, *qh, *ql, *kh, *kl, *vh, *vl, *wth, *wtl;
    cudaGetSymbolAddress((void**)&ah, g_ah);
    cudaGetSymbolAddress((void**)&al, g_al);
    cudaGetSymbolAddress((void**)&qh, g_qh);
    cudaGetSymbolAddress((void**)&ql, g_ql);
    cudaGetSymbolAddress((void**)&kh, g_kh);
    cudaGetSymbolAddress((void**)&kl, g_kl);
    cudaGetSymbolAddress((void**)&vh, g_vh);
    cudaGetSymbolAddress((void**)&vl, g_vl);
    cudaGetSymbolAddress((void**)&wth, g_wth);
    cudaGetSymbolAddress((void**)&wtl, g_wtl);

    cudaFuncSetAttribute(gemm_tc<0>, cudaFuncAttributeMaxDynamicSharedMemorySize, GSM_BYTES);
    cudaFuncSetAttribute(gemm_tc<1>, cudaFuncAttributeMaxDynamicSharedMemorySize, GSM_BYTES);
    cudaFuncSetAttribute(attn_mma_kernel, cudaFuncAttributeMaxDynamicSharedMemorySize, ASM_BYTES);

    const int NX = Mrows * Dd;

    split_kernel<<<NX / 256, 256>>>(x, ah, al, NX);
    splitW_kernel<<<dim3(32, 32, 4), dim3(32, 8)>>>(Wq, Wk, Wv, Wo, wth, wtl);

    gemm_tc<0><<<dim3(16, 64, 3), 256, GSM_BYTES>>>(
        ah, al, wth, wtl, nullptr, nullptr, qh, ql, kh, kl, vh, vl);

    attn_mma_kernel<<<dim3(Ss / 64, Bb * Hh), 128, ASM_BYTES>>>(
        qh, ql, kh, kl, vh, vl, ah, al);

    gemm_tc<1><<<dim3(16, 64), 256, GSM_BYTES>>>(
        ah, al, wth, wtl, bo, out,
        nullptr, nullptr, nullptr, nullptr, nullptr, nullptr);
}

// round 13
// speedup vs baseline: 9.4471x; 1.3642x over previous
#include <cuda_runtime.h>
#include <cuda_fp16.h>
#include <cstdint>

#define Bb 4
#define Ss 2048
#define Dd 1024
#define Hh 16
#define HDd 64
#define Mrows (Bb*Ss)   // 8192

// ---------------- scratch (device globals; no runtime allocation) ----------
__device__ __half g_ah[Mrows*Dd];   // x-split hi, later ctx-split hi
__device__ __half g_al[Mrows*Dd];   // x-split lo, later ctx-split lo
__device__ __half g_qh[Mrows*Dd], g_ql[Mrows*Dd];   // Q pre-scaled by 1/8
__device__ __half g_kh[Mrows*Dd];                   // K hi only
__device__ __half g_vh[Mrows*Dd];                   // V^T hi only: [b,h,d,s]
__device__ __half g_wth[4*Dd*Dd];                   // W^T hi only [w][n][k]

#define MMA16816R(Cf, Af, B0, B1) \
    asm volatile("mma.sync.aligned.m16n8k16.row.col.f32.f16.f16.f32 " \
        "{%0,%1,%2,%3}, {%4,%5,%6,%7}, {%8,%9}, {%0,%1,%2,%3};" \
        : "+f"(Cf[0]), "+f"(Cf[1]), "+f"(Cf[2]), "+f"(Cf[3]) \
        : "r"(Af[0]), "r"(Af[1]), "r"(Af[2]), "r"(Af[3]), \
          "r"(B0), "r"(B1))

#define LDSM4(r0, r1, r2, r3, addr) \
    asm volatile("ldmatrix.sync.aligned.m8n8.x4.shared.b16 {%0,%1,%2,%3}, [%4];" \
        : "=r"(r0), "=r"(r1), "=r"(r2), "=r"(r3) : "r"(addr))

__device__ __forceinline__ void split2h(float x, float y, uint32_t& hi, uint32_t& lo)
{
    __half hx = __float2half_rn(x), hy = __float2half_rn(y);
    float rx = x - __half2float(hx);
    float ry = y - __half2float(hy);
    __half2 h2(hx, hy);
    __half2 l2(__float2half_rn(rx), __float2half_rn(ry));
    hi = *reinterpret_cast<uint32_t*>(&h2);
    lo = *reinterpret_cast<uint32_t*>(&l2);
}

__device__ __forceinline__ uint32_t smaddr(const void* p) {
    uint32_t a;
    asm("{ .reg .u64 t; cvta.to.shared.u64 t, %1; cvt.u32.u64 %0, t; }"
        : "=r"(a) : "l"(p));
    return a;
}
__device__ __forceinline__ void cpa16(uint32_t dst, const void* src) {
    asm volatile("cp.async.cg.shared.global [%0], [%1], 16;" :: "r"(dst), "l"(src));
}
#define CP_COMMIT() asm volatile("cp.async.commit_group;")
#define CP_WAIT(n)  asm volatile("cp.async.wait_group %0;" :: "n"(n))

extern __shared__ __half dynsm[];

// ---------------------------------------------------------------------------
// split fp32 -> fp16 hi/lo (flat; used for x)
// ---------------------------------------------------------------------------
__global__ __launch_bounds__(256) void split_kernel(
    const float* __restrict__ in, __half* __restrict__ hi,
    __half* __restrict__ lo, int n)
{
    int i = blockIdx.x * 256 + threadIdx.x;
    if (i < n) {
        float x = in[i];
        __half h = __float2half_rn(x);
        hi[i] = h;
        lo[i] = __float2half_rn(x - __half2float(h));
    }
}

// ---------------------------------------------------------------------------
// transpose + fp16 all 4 weights: W[k][n] fp32 -> Wt[w][n][k] fp16 (hi only)
// ---------------------------------------------------------------------------
__global__ __launch_bounds__(256) void splitW_kernel(
    const float* __restrict__ W0, const float* __restrict__ W1,
    const float* __restrict__ W2, const float* __restrict__ W3,
    __half* __restrict__ th)
{
    __shared__ float tile[32][33];
    int w = blockIdx.z;
    const float* W = (w == 0) ? W0 : (w == 1) ? W1 : (w == 2) ? W2 : W3;
    int bx = blockIdx.x * 32;
    int by = blockIdx.y * 32;
    int tx = threadIdx.x, ty0 = threadIdx.y;

    #pragma unroll
    for (int j = 0; j < 4; j++) {
        int k = by + ty0 + j * 8;
        tile[ty0 + j * 8][tx] = W[(size_t)k * Dd + bx + tx];
    }
    __syncthreads();
    size_t base = (size_t)w * Dd * Dd;
    #pragma unroll
    for (int j = 0; j < 4; j++) {
        int n = bx + ty0 + j * 8;
        th[base + (size_t)n * Dd + by + tx] = __float2half_rn(tile[tx][ty0 + j * 8]);
    }
}

// ---------------------------------------------------------------------------
// Tensor-core 2-term fp16 GEMM: C = (Ah+Al)@Wh (+bias).
// Block tile 128x64, K-tile 64, 2-stage cp.async, 256 threads (8 warps 4x2),
// warp tile 32x32, ldmatrix fragment loads.
// smem halves, stride GS=72: Ah,Al: SM_A(hl,st) 128x72; Wh: SM_W(st) 64x72.
// ---------------------------------------------------------------------------
#define GS 72
#define SM_A(hl, st)  ((hl)*18432 + (st)*9216)
#define SM_W(st)      (36864 + (st)*4608)
#define GSM_BYTES 92160

template<int MODE>
__global__ __launch_bounds__(256) void gemm_tc(
    const __half* __restrict__ Ah, const __half* __restrict__ Al,
    const __half* __restrict__ Wth,
    const float* __restrict__ bias, float* __restrict__ outF,
    __half* __restrict__ oqh, __half* __restrict__ oql,
    __half* __restrict__ okh, __half* __restrict__ ovh)
{
    int t    = threadIdx.x;
    int lane = t & 31, wid = t >> 5;
    int wm   = wid >> 1, wn = wid & 1;
    int m0   = blockIdx.y * 128, n0 = blockIdx.x * 64;
    int tg   = lane & 3, gp = lane >> 2;
    int z    = (MODE == 0) ? blockIdx.z : 3;
    size_t wbase = (size_t)z * Dd * Dd;

    uint32_t smb = smaddr(dynsm);

    int aRow = lane & 15, aColH = (lane >> 4) * 8;
    int bRow = ((lane >> 4) & 1) * 8 + (lane & 7);
    int bColH = ((lane >> 3) & 1) * 8;
    int aoff = (wm * 32 + aRow) * GS + aColH;
    int boff0 = (wn * 32 + bRow) * GS + bColH;

    // stage: A 2048 chunks + W 512 chunks of 16B => 10 per thread
    auto stage_load = [&](int st, int k0) {
        #pragma unroll
        for (int e = 0; e < 10; e++) {
            int id = t + e * 256;
            uint32_t dst;
            const __half* src;
            if (id < 2048) {
                int hl = id >> 10, rem = id & 1023, r = rem >> 3, c = rem & 7;
                src = (hl ? Al : Ah) + (size_t)(m0 + r) * Dd + k0 + c * 8;
                dst = smb + 2 * (SM_A(hl, st) + r * GS + c * 8);
            } else {
                int id2 = id - 2048;
                int r = id2 >> 3, c = id2 & 7;
                src = Wth + wbase + (size_t)(n0 + r) * Dd + k0 + c * 8;
                dst = smb + 2 * (SM_W(st) + r * GS + c * 8);
            }
            cpa16(dst, src);
        }
        CP_COMMIT();
    };

    float acc[2][4][4] = {};

    stage_load(0, 0);
    for (int it = 0; it < 16; it++) {
        int cur = it & 1;
        if (it < 15) { stage_load(cur ^ 1, (it + 1) * 64); CP_WAIT(1); }
        else         { CP_WAIT(0); }
        __syncthreads();

        #pragma unroll
        for (int kh = 0; kh < 4; kh++) {
            uint32_t fah[2][4], fal[2][4];
            #pragma unroll
            for (int mi = 0; mi < 2; mi++) {
                uint32_t ah_ = smb + 2 * (SM_A(0, cur) + aoff + mi * 16 * GS + kh * 16);
                uint32_t al_ = smb + 2 * (SM_A(1, cur) + aoff + mi * 16 * GS + kh * 16);
                LDSM4(fah[mi][0], fah[mi][1], fah[mi][2], fah[mi][3], ah_);
                LDSM4(fal[mi][0], fal[mi][1], fal[mi][2], fal[mi][3], al_);
            }
            #pragma unroll
            for (int pair = 0; pair < 2; pair++) {
                uint32_t bh_ = smb + 2 * (SM_W(cur) + boff0 + pair * 16 * GS + kh * 16);
                uint32_t t0, t1, t2, t3;
                LDSM4(t0, t1, t2, t3, bh_);
                #pragma unroll
                for (int mi = 0; mi < 2; mi++) {
                    MMA16816R(acc[mi][2*pair],     fah[mi], t0, t1);
                    MMA16816R(acc[mi][2*pair],     fal[mi], t0, t1);
                    MMA16816R(acc[mi][2*pair + 1], fah[mi], t2, t3);
                    MMA16816R(acc[mi][2*pair + 1], fal[mi], t2, t3);
                }
            }
        }
        __syncthreads();
    }

    // ---- epilogue
    #pragma unroll
    for (int mi = 0; mi < 2; mi++) {
        int r1 = m0 + wm * 32 + mi * 16 + gp;
        #pragma unroll
        for (int ni = 0; ni < 4; ni++) {
            int cn = n0 + wn * 32 + ni * 8 + tg * 2;
            if (MODE == 1) {
                float b0 = bias[cn], b1 = bias[cn + 1];
                outF[(size_t)r1 * Dd + cn]           = acc[mi][ni][0] + b0;
                outF[(size_t)r1 * Dd + cn + 1]       = acc[mi][ni][1] + b1;
                outF[(size_t)(r1 + 8) * Dd + cn]     = acc[mi][ni][2] + b0;
                outF[(size_t)(r1 + 8) * Dd + cn + 1] = acc[mi][ni][3] + b1;
            } else if (z == 0) {
                // Q: pre-scale by 1/8 (exact), 2-term split
                uint32_t hw, lw;
                split2h(0.125f * acc[mi][ni][0], 0.125f * acc[mi][ni][1], hw, lw);
                *(uint32_t*)&oqh[(size_t)r1 * Dd + cn] = hw;
                *(uint32_t*)&oql[(size_t)r1 * Dd + cn] = lw;
                split2h(0.125f * acc[mi][ni][2], 0.125f * acc[mi][ni][3], hw, lw);
                *(uint32_t*)&oqh[(size_t)(r1 + 8) * Dd + cn] = hw;
                *(uint32_t*)&oql[(size_t)(r1 + 8) * Dd + cn] = lw;
            } else if (z == 1) {
                // K: hi only
                __half2 p0 = __floats2half2_rn(acc[mi][ni][0], acc[mi][ni][1]);
                __half2 p1 = __floats2half2_rn(acc[mi][ni][2], acc[mi][ni][3]);
                *(uint32_t*)&okh[(size_t)r1 * Dd + cn]       = *(uint32_t*)&p0;
                *(uint32_t*)&okh[(size_t)(r1 + 8) * Dd + cn] = *(uint32_t*)&p1;
            } else {
                // V transposed hi only: out[((b*16+h)*64 + d)][s], m=(b,s), n=(h,d)
                #pragma unroll
                for (int rr = 0; rr < 2; rr++) {
                    int m = r1 + rr * 8;
                    int bI = m >> 11, s = m & 2047;
                    #pragma unroll
                    for (int cc = 0; cc < 2; cc++) {
                        int n = cn + cc;
                        int hI = n >> 6, d = n & 63;
                        size_t idx = ((size_t)(bI * Hh + hI) * HDd + d) * Ss + s;
                        ovh[idx] = __float2half_rn(acc[mi][ni][rr * 2 + cc]);
                    }
                }
            }
        }
    }
}

// ---------------------------------------------------------------------------
// MMA flash attention (causal), fp16 2-term. K double-buffered, V single-
// buffered with post-sync prefetch. Q pre-scaled by 1/8 (no per-score mul).
// smem halves: Kh[st]: st*4608 (64x72); Vh: 9216. Total 27648 B; 4 blocks/SM.
// ---------------------------------------------------------------------------
#define VS 72
#define K_OFF(st) ((st) * 4608)
#define V_OFF     9216
#define ASM_BYTES 27648

__global__ __launch_bounds__(128, 4) void attn_mma_kernel(
    const __half* __restrict__ Qh, const __half* __restrict__ Ql,
    const __half* __restrict__ Kh, const __half* __restrict__ Vth,
    __half* __restrict__ Ch, __half* __restrict__ Cl)
{
    int t    = threadIdx.x;
    int lane = t & 31, w = t >> 5;
    int tg   = lane & 3, gp = lane >> 2;
    int qt   = (int)gridDim.x - 1 - (int)blockIdx.x;   // longest first
    int bh   = blockIdx.y;
    int b    = bh >> 4, h = bh & 15;
    int q0   = qt * 64;
    int rowL0 = w * 16 + gp;

    uint32_t smb = smaddr(dynsm);
    int bRow = ((lane >> 4) & 1) * 8 + (lane & 7);
    int bColH = ((lane >> 3) & 1) * 8;

    const __half* kbh0 = Kh + ((size_t)(b * Ss)) * Dd + h * HDd;
    const __half* vbh0 = Vth + ((size_t)(b * Hh + h) * HDd) * Ss;

    // 512 x 16B chunks each: 4 per thread
    auto stageK = [&](int kt, int st) {
        #pragma unroll
        for (int e = 0; e < 4; e++) {
            int id = t + e * 128;
            int r = id >> 3, c = id & 7;
            cpa16(smb + 2 * (K_OFF(st) + r * VS + c * 8),
                  kbh0 + (size_t)(kt * 64 + r) * Dd + c * 8);
        }
    };
    auto stageV = [&](int kt) {
        #pragma unroll
        for (int e = 0; e < 4; e++) {
            int id = t + e * 128;
            int r = id >> 3, c = id & 7;
            cpa16(smb + 2 * (V_OFF + r * VS + c * 8),
                  vbh0 + (size_t)r * Ss + kt * 64 + c * 8);
        }
    };

    // ---- Q fragments (pre-scaled, 2-term) from global
    uint32_t qhf[4][4], qlf[4][4];
    {
        const __half* qbh = Qh + ((size_t)(b * Ss + q0 + rowL0)) * Dd + h * HDd;
        const __half* qbl = Ql + ((size_t)(b * Ss + q0 + rowL0)) * Dd + h * HDd;
        #pragma unroll
        for (int s = 0; s < 4; s++) {
            int kc = s * 16 + tg * 2;
            qhf[s][0] = *(const uint32_t*)&qbh[kc];
            qhf[s][1] = *(const uint32_t*)&qbh[(size_t)8 * Dd + kc];
            qhf[s][2] = *(const uint32_t*)&qbh[kc + 8];
            qhf[s][3] = *(const uint32_t*)&qbh[(size_t)8 * Dd + kc + 8];
            qlf[s][0] = *(const uint32_t*)&qbl[kc];
            qlf[s][1] = *(const uint32_t*)&qbl[(size_t)8 * Dd + kc];
            qlf[s][2] = *(const uint32_t*)&qbl[kc + 8];
            qlf[s][3] = *(const uint32_t*)&qbl[(size_t)8 * Dd + kc + 8];
        }
    }

    float m0 = -1e30f, m1 = -1e30f;
    float l0 = 0.f,    l1 = 0.f;
    float o[8][4] = {};

    stageK(0, 0);
    stageV(0);
    CP_COMMIT();
    if (1 <= qt) stageK(1, 1);
    CP_COMMIT();

    for (int kt = 0; kt <= qt; kt++) {
        const bool diag = (kt == qt);
        const int st = kt & 1;
        if (kt < qt) CP_WAIT(1);   // drains K(kt)+V(kt); newest K may be in flight
        else         CP_WAIT(0);   // diag: drain everything (fixes qt==0 race)
        __syncthreads();

        // ---- S = Q K^T (2-term)
        float sc[8][4];
        #pragma unroll
        for (int ni = 0; ni < 8; ni++)
            sc[ni][0] = sc[ni][1] = sc[ni][2] = sc[ni][3] = 0.f;
        #pragma unroll
        for (int s = 0; s < 4; s++) {
            #pragma unroll
            for (int p = 0; p < 4; p++) {
                uint32_t kh_ = smb + 2 * (K_OFF(st) + (p * 16 + bRow) * VS + s * 16 + bColH);
                uint32_t t0, t1, t2, t3;
                LDSM4(t0, t1, t2, t3, kh_);
                MMA16816R(sc[2*p],     qhf[s], t0, t1);
                MMA16816R(sc[2*p],     qlf[s], t0, t1);
                MMA16816R(sc[2*p + 1], qhf[s], t2, t3);
                MMA16816R(sc[2*p + 1], qlf[s], t2, t3);
            }
        }

        // ---- mask + row max (scores already scaled via Q)
        float mx0 = -1e30f, mx1 = -1e30f;
        #pragma unroll
        for (int ni = 0; ni < 8; ni++) {
            int c0 = ni * 8 + tg * 2;
            float s0 = sc[ni][0], s1 = sc[ni][1];
            float s2 = sc[ni][2], s3 = sc[ni][3];
            if (diag) {
                if (c0     > rowL0)     s0 = -1e30f;
                if (c0 + 1 > rowL0)     s1 = -1e30f;
                if (c0     > rowL0 + 8) s2 = -1e30f;
                if (c0 + 1 > rowL0 + 8) s3 = -1e30f;
            }
            sc[ni][0] = s0; sc[ni][1] = s1; sc[ni][2] = s2; sc[ni][3] = s3;
            mx0 = fmaxf(mx0, fmaxf(s0, s1));
            mx1 = fmaxf(mx1, fmaxf(s2, s3));
        }
        mx0 = fmaxf(mx0, __shfl_xor_sync(0xffffffffu, mx0, 1));
        mx0 = fmaxf(mx0, __shfl_xor_sync(0xffffffffu, mx0, 2));
        mx1 = fmaxf(mx1, __shfl_xor_sync(0xffffffffu, mx1, 1));
        mx1 = fmaxf(mx1, __shfl_xor_sync(0xffffffffu, mx1, 2));

        float mn0 = fmaxf(m0, mx0), mn1 = fmaxf(m1, mx1);
        float a0 = __expf(m0 - mn0), a1 = __expf(m1 - mn1);
        m0 = mn0; m1 = mn1;
        l0 *= a0; l1 *= a1;
        #pragma unroll
        for (int ni = 0; ni < 8; ni++) {
            o[ni][0] *= a0; o[ni][1] *= a0;
            o[ni][2] *= a1; o[ni][3] *= a1;
        }

        // ---- P = exp(S - m)
        #pragma unroll
        for (int ni = 0; ni < 8; ni++) {
            float p0 = __expf(sc[ni][0] - m0);
            float p1 = __expf(sc[ni][1] - m0);
            float p2 = __expf(sc[ni][2] - m1);
            float p3 = __expf(sc[ni][3] - m1);
            l0 += p0 + p1; l1 += p2 + p3;
            sc[ni][0] = p0; sc[ni][1] = p1; sc[ni][2] = p2; sc[ni][3] = p3;
        }

        // ---- O += P V (2-term P, hi V)
        #pragma unroll
        for (int s = 0; s < 4; s++) {
            uint32_t pah[4], pal[4];
            split2h(sc[2*s][0],     sc[2*s][1],     pah[0], pal[0]);
            split2h(sc[2*s][2],     sc[2*s][3],     pah[1], pal[1]);
            split2h(sc[2*s + 1][0], sc[2*s + 1][1], pah[2], pal[2]);
            split2h(sc[2*s + 1][2], sc[2*s + 1][3], pah[3], pal[3]);
            #pragma unroll
            for (int p = 0; p < 4; p++) {
                uint32_t vh_ = smb + 2 * (V_OFF + (p * 16 + bRow) * VS + s * 16 + bColH);
                uint32_t t0, t1, t2, t3;
                LDSM4(t0, t1, t2, t3, vh_);
                MMA16816R(o[2*p],     pah, t0, t1);
                MMA16816R(o[2*p],     pal, t0, t1);
                MMA16816R(o[2*p + 1], pah, t2, t3);
                MMA16816R(o[2*p + 1], pal, t2, t3);
            }
        }
        __syncthreads();    // everyone done with V(kt), K(kt)

        if (kt < qt) {
            stageV(kt + 1);
            CP_COMMIT();
            if (kt + 2 <= qt) stageK(kt + 2, (kt + 2) & 1);
            CP_COMMIT();
        }
    }

    // ---- finalize + 2-term ctx output
    l0 += __shfl_xor_sync(0xffffffffu, l0, 1);
    l0 += __shfl_xor_sync(0xffffffffu, l0, 2);
    l1 += __shfl_xor_sync(0xffffffffu, l1, 1);
    l1 += __shfl_xor_sync(0xffffffffu, l1, 2);
    float inv0 = 1.f / l0, inv1 = 1.f / l1;

    __half* obh = Ch + ((size_t)(b * Ss + q0 + rowL0)) * Dd + h * HDd;
    __half* obl = Cl + ((size_t)(b * Ss + q0 + rowL0)) * Dd + h * HDd;
    #pragma unroll
    for (int ni = 0; ni < 8; ni++) {
        int c = ni * 8 + tg * 2;
        uint32_t hw, lw;
        split2h(o[ni][0] * inv0, o[ni][1] * inv0, hw, lw);
        *(uint32_t*)&obh[c] = hw;
        *(uint32_t*)&obl[c] = lw;
        split2h(o[ni][2] * inv1, o[ni][3] * inv1, hw, lw);
        *(uint32_t*)&obh[(size_t)8 * Dd + c] = hw;
        *(uint32_t*)&obl[(size_t)8 * Dd + c] = lw;
    }
}

// ---------------------------------------------------------------------------
extern "C" void kernel_launch(void* const* d_in, const int* in_sizes, int n_in,
                              void* d_out, int out_size)
{
    const float* x  = (const float*)d_in[0];
    const float* Wq = (const float*)d_in[1];
    const float* Wk = (const float*)d_in[2];
    const float* Wv = (const float*)d_in[3];
    const float* Wo = (const float*)d_in[4];
    const float* bo = (const float*)d_in[5];
    float* out = (float*)d_out;

    __half *ah, *al, *qh, *ql, *kh, *vh, *wth;
    cudaGetSymbolAddress((void**)&ah, g_ah);
    cudaGetSymbolAddress((void**)&al, g_al);
    cudaGetSymbolAddress((void**)&qh, g_qh);
    cudaGetSymbolAddress((void**)&ql, g_ql);
    cudaGetSymbolAddress((void**)&kh, g_kh);
    cudaGetSymbolAddress((void**)&vh, g_vh);
    cudaGetSymbolAddress((void**)&wth, g_wth);

    cudaFuncSetAttribute(gemm_tc<0>, cudaFuncAttributeMaxDynamicSharedMemorySize, GSM_BYTES);
    cudaFuncSetAttribute(gemm_tc<1>, cudaFuncAttributeMaxDynamicSharedMemorySize, GSM_BYTES);
    cudaFuncSetAttribute(attn_mma_kernel, cudaFuncAttributeMaxDynamicSharedMemorySize, ASM_BYTES);

    const int NX = Mrows * Dd;

    split_kernel<<<NX / 256, 256>>>(x, ah, al, NX);
    splitW_kernel<<<dim3(32, 32, 4), dim3(32, 8)>>>(Wq, Wk, Wv, Wo, wth);

    // fused QKV projections (z selects weight/output)
    gemm_tc<0><<<dim3(16, 64, 3), 256, GSM_BYTES>>>(
        ah, al, wth, nullptr, nullptr, qh, ql, kh, vh);

    // attention writes 2-term ctx into ah/al
    attn_mma_kernel<<<dim3(Ss / 64, Bb * Hh), 128, ASM_BYTES>>>(
        qh, ql, kh, vh, ah, al);

    // output projection
    gemm_tc<1><<<dim3(16, 64), 256, GSM_BYTES>>>(
        ah, al, wth, bo, out, nullptr, nullptr, nullptr, nullptr);
}

// round 14
// speedup vs baseline: 11.2016x; 1.1857x over previous
#include <cuda_runtime.h>
#include <cuda_fp16.h>
#include <cstdint>

#define Bb 4
#define Ss 2048
#define Dd 1024
#define Hh 16
#define HDd 64
#define Mrows (Bb*Ss)   // 8192

// ---------------- scratch (device globals; no runtime allocation) ----------
__device__ __half g_ah[Mrows*Dd];   // x-split hi, later ctx-split hi
__device__ __half g_al[Mrows*Dd];   // x-split lo, later ctx-split lo
__device__ __half g_qh[Mrows*Dd], g_ql[Mrows*Dd];   // Q pre-scaled by 1/8
__device__ __half g_kh[Mrows*Dd];                   // K hi only
__device__ __half g_vh[Mrows*Dd];                   // V^T hi only: [b,h,d,s]
__device__ __half g_wth[4*Dd*Dd];                   // W^T hi only [w][n][k]

#define MMA16816R(Cf, Af, B0, B1) \
    asm volatile("mma.sync.aligned.m16n8k16.row.col.f32.f16.f16.f32 " \
        "{%0,%1,%2,%3}, {%4,%5,%6,%7}, {%8,%9}, {%0,%1,%2,%3};" \
        : "+f"(Cf[0]), "+f"(Cf[1]), "+f"(Cf[2]), "+f"(Cf[3]) \
        : "r"(Af[0]), "r"(Af[1]), "r"(Af[2]), "r"(Af[3]), \
          "r"(B0), "r"(B1))

#define LDSM4(r0, r1, r2, r3, addr) \
    asm volatile("ldmatrix.sync.aligned.m8n8.x4.shared.b16 {%0,%1,%2,%3}, [%4];" \
        : "=r"(r0), "=r"(r1), "=r"(r2), "=r"(r3) : "r"(addr))

__device__ __forceinline__ void split2h(float x, float y, uint32_t& hi, uint32_t& lo)
{
    __half hx = __float2half_rn(x), hy = __float2half_rn(y);
    float rx = x - __half2float(hx);
    float ry = y - __half2float(hy);
    __half2 h2(hx, hy);
    __half2 l2(__float2half_rn(rx), __float2half_rn(ry));
    hi = *reinterpret_cast<uint32_t*>(&h2);
    lo = *reinterpret_cast<uint32_t*>(&l2);
}

__device__ __forceinline__ uint32_t pack2h(float x, float y)
{
    __half2 h2 = __floats2half2_rn(x, y);
    return *reinterpret_cast<uint32_t*>(&h2);
}

__device__ __forceinline__ uint32_t smaddr(const void* p) {
    uint32_t a;
    asm("{ .reg .u64 t; cvta.to.shared.u64 t, %1; cvt.u32.u64 %0, t; }"
        : "=r"(a) : "l"(p));
    return a;
}
__device__ __forceinline__ void cpa16(uint32_t dst, const void* src) {
    asm volatile("cp.async.cg.shared.global [%0], [%1], 16;" :: "r"(dst), "l"(src));
}
#define CP_COMMIT() asm volatile("cp.async.commit_group;")
#define CP_WAIT(n)  asm volatile("cp.async.wait_group %0;" :: "n"(n))

extern __shared__ __half dynsm[];

// ---------------------------------------------------------------------------
// split fp32 -> fp16 hi/lo (flat; used for x)
// ---------------------------------------------------------------------------
__global__ __launch_bounds__(256) void split_kernel(
    const float* __restrict__ in, __half* __restrict__ hi,
    __half* __restrict__ lo, int n)
{
    int i = blockIdx.x * 256 + threadIdx.x;
    if (i < n) {
        float x = in[i];
        __half h = __float2half_rn(x);
        hi[i] = h;
        lo[i] = __float2half_rn(x - __half2float(h));
    }
}

// ---------------------------------------------------------------------------
// transpose + fp16 all 4 weights: W[k][n] fp32 -> Wt[w][n][k] fp16 (hi only)
// ---------------------------------------------------------------------------
__global__ __launch_bounds__(256) void splitW_kernel(
    const float* __restrict__ W0, const float* __restrict__ W1,
    const float* __restrict__ W2, const float* __restrict__ W3,
    __half* __restrict__ th)
{
    __shared__ float tile[32][33];
    int w = blockIdx.z;
    const float* W = (w == 0) ? W0 : (w == 1) ? W1 : (w == 2) ? W2 : W3;
    int bx = blockIdx.x * 32;
    int by = blockIdx.y * 32;
    int tx = threadIdx.x, ty0 = threadIdx.y;

    #pragma unroll
    for (int j = 0; j < 4; j++) {
        int k = by + ty0 + j * 8;
        tile[ty0 + j * 8][tx] = W[(size_t)k * Dd + bx + tx];
    }
    __syncthreads();
    size_t base = (size_t)w * Dd * Dd;
    #pragma unroll
    for (int j = 0; j < 4; j++) {
        int n = bx + ty0 + j * 8;
        th[base + (size_t)n * Dd + by + tx] = __float2half_rn(tile[tx][ty0 + j * 8]);
    }
}

// ---------------------------------------------------------------------------
// Tensor-core 2-term fp16 GEMM: C = (Ah+Al)@Wh (+bias).
// Block tile 128x128, K-tile 64, 2-stage cp.async, 256 threads (8 warps 4x2),
// warp tile 32x64. MMA:LDSM = 32:8 per k16 step.
// smem halves, stride GS=72: Ah,Al: SM_A(hl,st) 128x72; Wh: SM_W(st) 128x72.
// ---------------------------------------------------------------------------
#define GS 72
#define SM_A(hl, st)  ((hl)*18432 + (st)*9216)
#define SM_W(st)      (36864 + (st)*9216)
#define GSM_BYTES 110592

template<int MODE>
__global__ __launch_bounds__(256, 2) void gemm_tc(
    const __half* __restrict__ Ah, const __half* __restrict__ Al,
    const __half* __restrict__ Wth,
    const float* __restrict__ bias, float* __restrict__ outF,
    __half* __restrict__ oqh, __half* __restrict__ oql,
    __half* __restrict__ okh, __half* __restrict__ ovh)
{
    int t    = threadIdx.x;
    int lane = t & 31, wid = t >> 5;
    int wm   = wid >> 1, wn = wid & 1;
    int m0   = blockIdx.y * 128, n0 = blockIdx.x * 128;
    int tg   = lane & 3, gp = lane >> 2;
    int z    = (MODE == 0) ? blockIdx.z : 3;
    size_t wbase = (size_t)z * Dd * Dd;

    uint32_t smb = smaddr(dynsm);

    int aRow = lane & 15, aColH = (lane >> 4) * 8;
    int bRow = ((lane >> 4) & 1) * 8 + (lane & 7);
    int bColH = ((lane >> 3) & 1) * 8;
    int aoff = (wm * 32 + aRow) * GS + aColH;
    int boff0 = (wn * 64 + bRow) * GS + bColH;

    // stage: A 2048 chunks + W 1024 chunks of 16B => 12 per thread
    auto stage_load = [&](int st, int k0) {
        #pragma unroll
        for (int e = 0; e < 12; e++) {
            int id = t + e * 256;
            uint32_t dst;
            const __half* src;
            if (id < 2048) {
                int hl = id >> 10, rem = id & 1023, r = rem >> 3, c = rem & 7;
                src = (hl ? Al : Ah) + (size_t)(m0 + r) * Dd + k0 + c * 8;
                dst = smb + 2 * (SM_A(hl, st) + r * GS + c * 8);
            } else {
                int id2 = id - 2048;
                int r = id2 >> 3, c = id2 & 7;
                src = Wth + wbase + (size_t)(n0 + r) * Dd + k0 + c * 8;
                dst = smb + 2 * (SM_W(st) + r * GS + c * 8);
            }
            cpa16(dst, src);
        }
        CP_COMMIT();
    };

    float acc[2][8][4] = {};

    stage_load(0, 0);
    for (int it = 0; it < 16; it++) {
        int cur = it & 1;
        if (it < 15) { stage_load(cur ^ 1, (it + 1) * 64); CP_WAIT(1); }
        else         { CP_WAIT(0); }
        __syncthreads();

        #pragma unroll
        for (int kh = 0; kh < 4; kh++) {
            uint32_t fah[2][4], fal[2][4];
            #pragma unroll
            for (int mi = 0; mi < 2; mi++) {
                uint32_t ah_ = smb + 2 * (SM_A(0, cur) + aoff + mi * 16 * GS + kh * 16);
                uint32_t al_ = smb + 2 * (SM_A(1, cur) + aoff + mi * 16 * GS + kh * 16);
                LDSM4(fah[mi][0], fah[mi][1], fah[mi][2], fah[mi][3], ah_);
                LDSM4(fal[mi][0], fal[mi][1], fal[mi][2], fal[mi][3], al_);
            }
            #pragma unroll
            for (int pair = 0; pair < 4; pair++) {
                uint32_t bh_ = smb + 2 * (SM_W(cur) + boff0 + pair * 16 * GS + kh * 16);
                uint32_t t0, t1, t2, t3;
                LDSM4(t0, t1, t2, t3, bh_);
                #pragma unroll
                for (int mi = 0; mi < 2; mi++) {
                    MMA16816R(acc[mi][2*pair],     fah[mi], t0, t1);
                    MMA16816R(acc[mi][2*pair],     fal[mi], t0, t1);
                    MMA16816R(acc[mi][2*pair + 1], fah[mi], t2, t3);
                    MMA16816R(acc[mi][2*pair + 1], fal[mi], t2, t3);
                }
            }
        }
        __syncthreads();
    }

    // ---- epilogue
    #pragma unroll
    for (int mi = 0; mi < 2; mi++) {
        int r1 = m0 + wm * 32 + mi * 16 + gp;
        #pragma unroll
        for (int ni = 0; ni < 8; ni++) {
            int cn = n0 + wn * 64 + ni * 8 + tg * 2;
            if (MODE == 1) {
                float b0 = bias[cn], b1 = bias[cn + 1];
                outF[(size_t)r1 * Dd + cn]           = acc[mi][ni][0] + b0;
                outF[(size_t)r1 * Dd + cn + 1]       = acc[mi][ni][1] + b1;
                outF[(size_t)(r1 + 8) * Dd + cn]     = acc[mi][ni][2] + b0;
                outF[(size_t)(r1 + 8) * Dd + cn + 1] = acc[mi][ni][3] + b1;
            } else if (z == 0) {
                // Q: pre-scale by 1/8 (exact), 2-term split
                uint32_t hw, lw;
                split2h(0.125f * acc[mi][ni][0], 0.125f * acc[mi][ni][1], hw, lw);
                *(uint32_t*)&oqh[(size_t)r1 * Dd + cn] = hw;
                *(uint32_t*)&oql[(size_t)r1 * Dd + cn] = lw;
                split2h(0.125f * acc[mi][ni][2], 0.125f * acc[mi][ni][3], hw, lw);
                *(uint32_t*)&oqh[(size_t)(r1 + 8) * Dd + cn] = hw;
                *(uint32_t*)&oql[(size_t)(r1 + 8) * Dd + cn] = lw;
            } else if (z == 1) {
                // K: hi only
                *(uint32_t*)&okh[(size_t)r1 * Dd + cn] =
                    pack2h(acc[mi][ni][0], acc[mi][ni][1]);
                *(uint32_t*)&okh[(size_t)(r1 + 8) * Dd + cn] =
                    pack2h(acc[mi][ni][2], acc[mi][ni][3]);
            } else {
                // V transposed hi only: out[((b*16+h)*64 + d)][s], m=(b,s), n=(h,d)
                #pragma unroll
                for (int rr = 0; rr < 2; rr++) {
                    int m = r1 + rr * 8;
                    int bI = m >> 11, s = m & 2047;
                    #pragma unroll
                    for (int cc = 0; cc < 2; cc++) {
                        int n = cn + cc;
                        int hI = n >> 6, d = n & 63;
                        size_t idx = ((size_t)(bI * Hh + hI) * HDd + d) * Ss + s;
                        ovh[idx] = __float2half_rn(acc[mi][ni][rr * 2 + cc]);
                    }
                }
            }
        }
    }
}

// ---------------------------------------------------------------------------
// MMA flash attention (causal), fp16. K double-buffered, V single-buffered
// with post-sync prefetch. Q 2-term (pre-scaled by 1/8); K, V, P hi-only.
// smem halves: Kh[st]: st*4608 (64x72); Vh: 9216. Total 27648 B; 4 blocks/SM.
// ---------------------------------------------------------------------------
#define VS 72
#define K_OFF(st) ((st) * 4608)
#define V_OFF     9216
#define ASM_BYTES 27648

__global__ __launch_bounds__(128, 4) void attn_mma_kernel(
    const __half* __restrict__ Qh, const __half* __restrict__ Ql,
    const __half* __restrict__ Kh, const __half* __restrict__ Vth,
    __half* __restrict__ Ch, __half* __restrict__ Cl)
{
    int t    = threadIdx.x;
    int lane = t & 31, w = t >> 5;
    int tg   = lane & 3, gp = lane >> 2;
    int qt   = (int)gridDim.x - 1 - (int)blockIdx.x;   // longest first
    int bh   = blockIdx.y;
    int b    = bh >> 4, h = bh & 15;
    int q0   = qt * 64;
    int rowL0 = w * 16 + gp;

    uint32_t smb = smaddr(dynsm);
    int bRow = ((lane >> 4) & 1) * 8 + (lane & 7);
    int bColH = ((lane >> 3) & 1) * 8;

    const __half* kbh0 = Kh + ((size_t)(b * Ss)) * Dd + h * HDd;
    const __half* vbh0 = Vth + ((size_t)(b * Hh + h) * HDd) * Ss;

    // 512 x 16B chunks each: 4 per thread
    auto stageK = [&](int kt, int st) {
        #pragma unroll
        for (int e = 0; e < 4; e++) {
            int id = t + e * 128;
            int r = id >> 3, c = id & 7;
            cpa16(smb + 2 * (K_OFF(st) + r * VS + c * 8),
                  kbh0 + (size_t)(kt * 64 + r) * Dd + c * 8);
        }
    };
    auto stageV = [&](int kt) {
        #pragma unroll
        for (int e = 0; e < 4; e++) {
            int id = t + e * 128;
            int r = id >> 3, c = id & 7;
            cpa16(smb + 2 * (V_OFF + r * VS + c * 8),
                  vbh0 + (size_t)r * Ss + kt * 64 + c * 8);
        }
    };

    // ---- Q fragments (pre-scaled, 2-term) from global
    uint32_t qhf[4][4], qlf[4][4];
    {
        const __half* qbh = Qh + ((size_t)(b * Ss + q0 + rowL0)) * Dd + h * HDd;
        const __half* qbl = Ql + ((size_t)(b * Ss + q0 + rowL0)) * Dd + h * HDd;
        #pragma unroll
        for (int s = 0; s < 4; s++) {
            int kc = s * 16 + tg * 2;
            qhf[s][0] = *(const uint32_t*)&qbh[kc];
            qhf[s][1] = *(const uint32_t*)&qbh[(size_t)8 * Dd + kc];
            qhf[s][2] = *(const uint32_t*)&qbh[kc + 8];
            qhf[s][3] = *(const uint32_t*)&qbh[(size_t)8 * Dd + kc + 8];
            qlf[s][0] = *(const uint32_t*)&qbl[kc];
            qlf[s][1] = *(const uint32_t*)&qbl[(size_t)8 * Dd + kc];
            qlf[s][2] = *(const uint32_t*)&qbl[kc + 8];
            qlf[s][3] = *(const uint32_t*)&qbl[(size_t)8 * Dd + kc + 8];
        }
    }

    float m0 = -1e30f, m1 = -1e30f;
    float l0 = 0.f,    l1 = 0.f;
    float o[8][4] = {};

    stageK(0, 0);
    stageV(0);
    CP_COMMIT();
    if (1 <= qt) stageK(1, 1);
    CP_COMMIT();

    for (int kt = 0; kt <= qt; kt++) {
        const bool diag = (kt == qt);
        const int st = kt & 1;
        if (kt < qt) CP_WAIT(1);   // drains K(kt)+V(kt)
        else         CP_WAIT(0);   // diag: drain everything
        __syncthreads();

        // ---- S = Q K^T (2-term)
        float sc[8][4];
        #pragma unroll
        for (int ni = 0; ni < 8; ni++)
            sc[ni][0] = sc[ni][1] = sc[ni][2] = sc[ni][3] = 0.f;
        #pragma unroll
        for (int s = 0; s < 4; s++) {
            #pragma unroll
            for (int p = 0; p < 4; p++) {
                uint32_t kh_ = smb + 2 * (K_OFF(st) + (p * 16 + bRow) * VS + s * 16 + bColH);
                uint32_t t0, t1, t2, t3;
                LDSM4(t0, t1, t2, t3, kh_);
                MMA16816R(sc[2*p],     qhf[s], t0, t1);
                MMA16816R(sc[2*p],     qlf[s], t0, t1);
                MMA16816R(sc[2*p + 1], qhf[s], t2, t3);
                MMA16816R(sc[2*p + 1], qlf[s], t2, t3);
            }
        }

        // ---- mask + row max (scores already scaled via Q)
        float mx0 = -1e30f, mx1 = -1e30f;
        #pragma unroll
        for (int ni = 0; ni < 8; ni++) {
            int c0 = ni * 8 + tg * 2;
            float s0 = sc[ni][0], s1 = sc[ni][1];
            float s2 = sc[ni][2], s3 = sc[ni][3];
            if (diag) {
                if (c0     > rowL0)     s0 = -1e30f;
                if (c0 + 1 > rowL0)     s1 = -1e30f;
                if (c0     > rowL0 + 8) s2 = -1e30f;
                if (c0 + 1 > rowL0 + 8) s3 = -1e30f;
            }
            sc[ni][0] = s0; sc[ni][1] = s1; sc[ni][2] = s2; sc[ni][3] = s3;
            mx0 = fmaxf(mx0, fmaxf(s0, s1));
            mx1 = fmaxf(mx1, fmaxf(s2, s3));
        }
        mx0 = fmaxf(mx0, __shfl_xor_sync(0xffffffffu, mx0, 1));
        mx0 = fmaxf(mx0, __shfl_xor_sync(0xffffffffu, mx0, 2));
        mx1 = fmaxf(mx1, __shfl_xor_sync(0xffffffffu, mx1, 1));
        mx1 = fmaxf(mx1, __shfl_xor_sync(0xffffffffu, mx1, 2));

        float mn0 = fmaxf(m0, mx0), mn1 = fmaxf(m1, mx1);
        float a0 = __expf(m0 - mn0), a1 = __expf(m1 - mn1);
        m0 = mn0; m1 = mn1;
        l0 *= a0; l1 *= a1;
        #pragma unroll
        for (int ni = 0; ni < 8; ni++) {
            o[ni][0] *= a0; o[ni][1] *= a0;
            o[ni][2] *= a1; o[ni][3] *= a1;
        }

        // ---- P = exp(S - m)
        #pragma unroll
        for (int ni = 0; ni < 8; ni++) {
            float p0 = __expf(sc[ni][0] - m0);
            float p1 = __expf(sc[ni][1] - m0);
            float p2 = __expf(sc[ni][2] - m1);
            float p3 = __expf(sc[ni][3] - m1);
            l0 += p0 + p1; l1 += p2 + p3;
            sc[ni][0] = p0; sc[ni][1] = p1; sc[ni][2] = p2; sc[ni][3] = p3;
        }

        // ---- O += P V (hi-only P, hi V)
        #pragma unroll
        for (int s = 0; s < 4; s++) {
            uint32_t pah[4];
            pah[0] = pack2h(sc[2*s][0],     sc[2*s][1]);
            pah[1] = pack2h(sc[2*s][2],     sc[2*s][3]);
            pah[2] = pack2h(sc[2*s + 1][0], sc[2*s + 1][1]);
            pah[3] = pack2h(sc[2*s + 1][2], sc[2*s + 1][3]);
            #pragma unroll
            for (int p = 0; p < 4; p++) {
                uint32_t vh_ = smb + 2 * (V_OFF + (p * 16 + bRow) * VS + s * 16 + bColH);
                uint32_t t0, t1, t2, t3;
                LDSM4(t0, t1, t2, t3, vh_);
                MMA16816R(o[2*p],     pah, t0, t1);
                MMA16816R(o[2*p + 1], pah, t2, t3);
            }
        }
        __syncthreads();    // everyone done with V(kt), K(kt)

        if (kt < qt) {
            stageV(kt + 1);
            CP_COMMIT();
            if (kt + 2 <= qt) stageK(kt + 2, (kt + 2) & 1);
            CP_COMMIT();
        }
    }

    // ---- finalize + 2-term ctx output
    l0 += __shfl_xor_sync(0xffffffffu, l0, 1);
    l0 += __shfl_xor_sync(0xffffffffu, l0, 2);
    l1 += __shfl_xor_sync(0xffffffffu, l1, 1);
    l1 += __shfl_xor_sync(0xffffffffu, l1, 2);
    float inv0 = 1.f / l0, inv1 = 1.f / l1;

    __half* obh = Ch + ((size_t)(b * Ss + q0 + rowL0)) * Dd + h * HDd;
    __half* obl = Cl + ((size_t)(b * Ss + q0 + rowL0)) * Dd + h * HDd;
    #pragma unroll
    for (int ni = 0; ni < 8; ni++) {
        int c = ni * 8 + tg * 2;
        uint32_t hw, lw;
        split2h(o[ni][0] * inv0, o[ni][1] * inv0, hw, lw);
        *(uint32_t*)&obh[c] = hw;
        *(uint32_t*)&obl[c] = lw;
        split2h(o[ni][2] * inv1, o[ni][3] * inv1, hw, lw);
        *(uint32_t*)&obh[(size_t)8 * Dd + c] = hw;
        *(uint32_t*)&obl[(size_t)8 * Dd + c] = lw;
    }
}

// ---------------------------------------------------------------------------
extern "C" void kernel_launch(void* const* d_in, const int* in_sizes, int n_in,
                              void* d_out, int out_size)
{
    const float* x  = (const float*)d_in[0];
    const float* Wq = (const float*)d_in[1];
    const float* Wk = (const float*)d_in[2];
    const float* Wv = (const float*)d_in[3];
    const float* Wo = (const float*)d_in[4];
    const float* bo = (const float*)d_in[5];
    float* out = (float*)d_out;

    __half *ah, *al, *qh, *ql, *kh, *vh, *wth;
    cudaGetSymbolAddress((void**)&ah, g_ah);
    cudaGetSymbolAddress((void**)&al, g_al);
    cudaGetSymbolAddress((void**)&qh, g_qh);
    cudaGetSymbolAddress((void**)&ql, g_ql);
    cudaGetSymbolAddress((void**)&kh, g_kh);
    cudaGetSymbolAddress((void**)&vh, g_vh);
    cudaGetSymbolAddress((void**)&wth, g_wth);

    cudaFuncSetAttribute(gemm_tc<0>, cudaFuncAttributeMaxDynamicSharedMemorySize, GSM_BYTES);
    cudaFuncSetAttribute(gemm_tc<1>, cudaFuncAttributeMaxDynamicSharedMemorySize, GSM_BYTES);
    cudaFuncSetAttribute(attn_mma_kernel, cudaFuncAttributeMaxDynamicSharedMemorySize, ASM_BYTES);

    const int NX = Mrows * Dd;

    split_kernel<<<NX / 256, 256>>>(x, ah, al, NX);
    splitW_kernel<<<dim3(32, 32, 4), dim3(32, 8)>>>(Wq, Wk, Wv, Wo, wth);

    // fused QKV projections (z selects weight/output); N-tiles now 128 wide
    gemm_tc<0><<<dim3(8, 64, 3), 256, GSM_BYTES>>>(
        ah, al, wth, nullptr, nullptr, qh, ql, kh, vh);

    // attention writes 2-term ctx into ah/al
    attn_mma_kernel<<<dim3(Ss / 64, Bb * Hh), 128, ASM_BYTES>>>(
        qh, ql, kh, vh, ah, al);

    // output projection
    gemm_tc<1><<<dim3(8, 64), 256, GSM_BYTES>>>(
        ah, al, wth, bo, out, nullptr, nullptr, nullptr, nullptr);
}

// round 15
// speedup vs baseline: 16.8570x; 1.5049x over previous
#include <cuda_runtime.h>
#include <cuda_fp16.h>
#include <cstdint>

#define Bb 4
#define Ss 2048
#define Dd 1024
#define Hh 16
#define HDd 64
#define Mrows (Bb*Ss)   // 8192

// ---------------- scratch (device globals; no runtime allocation) ----------
__device__ __half g_ah[Mrows*Dd];   // x hi, later ctx hi
__device__ __half g_qh[Mrows*Dd];   // Q pre-scaled by 1/8
__device__ __half g_kh[Mrows*Dd];   // K
__device__ __half g_vh[Mrows*Dd];   // V^T: [b,h,d,s]
__device__ __half g_wth[4*Dd*Dd];   // W^T [w][n][k]

#define MMA16816R(Cf, Af, B0, B1) \
    asm volatile("mma.sync.aligned.m16n8k16.row.col.f32.f16.f16.f32 " \
        "{%0,%1,%2,%3}, {%4,%5,%6,%7}, {%8,%9}, {%0,%1,%2,%3};" \
        : "+f"(Cf[0]), "+f"(Cf[1]), "+f"(Cf[2]), "+f"(Cf[3]) \
        : "r"(Af[0]), "r"(Af[1]), "r"(Af[2]), "r"(Af[3]), \
          "r"(B0), "r"(B1))

#define LDSM4(r0, r1, r2, r3, addr) \
    asm volatile("ldmatrix.sync.aligned.m8n8.x4.shared.b16 {%0,%1,%2,%3}, [%4];" \
        : "=r"(r0), "=r"(r1), "=r"(r2), "=r"(r3) : "r"(addr))

__device__ __forceinline__ uint32_t pack2h(float x, float y)
{
    __half2 h2 = __floats2half2_rn(x, y);
    return *reinterpret_cast<uint32_t*>(&h2);
}

__device__ __forceinline__ uint32_t smaddr(const void* p) {
    uint32_t a;
    asm("{ .reg .u64 t; cvta.to.shared.u64 t, %1; cvt.u32.u64 %0, t; }"
        : "=r"(a) : "l"(p));
    return a;
}
__device__ __forceinline__ void cpa16(uint32_t dst, const void* src) {
    asm volatile("cp.async.cg.shared.global [%0], [%1], 16;" :: "r"(dst), "l"(src));
}
#define CP_COMMIT() asm volatile("cp.async.commit_group;")
#define CP_WAIT(n)  asm volatile("cp.async.wait_group %0;" :: "n"(n))

extern __shared__ __half dynsm[];

// ---------------------------------------------------------------------------
// fp32 -> fp16 convert (flat; used for x)
// ---------------------------------------------------------------------------
__global__ __launch_bounds__(256) void tofp16_kernel(
    const float* __restrict__ in, __half* __restrict__ out, int n)
{
    int i = blockIdx.x * 256 + threadIdx.x;
    if (i < n) out[i] = __float2half_rn(in[i]);
}

// ---------------------------------------------------------------------------
// transpose + fp16 all 4 weights: W[k][n] fp32 -> Wt[w][n][k] fp16
// ---------------------------------------------------------------------------
__global__ __launch_bounds__(256) void splitW_kernel(
    const float* __restrict__ W0, const float* __restrict__ W1,
    const float* __restrict__ W2, const float* __restrict__ W3,
    __half* __restrict__ th)
{
    __shared__ float tile[32][33];
    int w = blockIdx.z;
    const float* W = (w == 0) ? W0 : (w == 1) ? W1 : (w == 2) ? W2 : W3;
    int bx = blockIdx.x * 32;
    int by = blockIdx.y * 32;
    int tx = threadIdx.x, ty0 = threadIdx.y;

    #pragma unroll
    for (int j = 0; j < 4; j++) {
        int k = by + ty0 + j * 8;
        tile[ty0 + j * 8][tx] = W[(size_t)k * Dd + bx + tx];
    }
    __syncthreads();
    size_t base = (size_t)w * Dd * Dd;
    #pragma unroll
    for (int j = 0; j < 4; j++) {
        int n = bx + ty0 + j * 8;
        th[base + (size_t)n * Dd + by + tx] = __float2half_rn(tile[tx][ty0 + j * 8]);
    }
}

// ---------------------------------------------------------------------------
// Tensor-core fp16 GEMM: C = Ah@Wh (+bias), fp32 accumulate.
// Block tile 128x128, K-tile 64, 2-stage cp.async, 256 threads (8 warps 4x2),
// warp tile 32x64, ldmatrix fragment loads.
// smem halves, stride GS=72: A: SM_A(st) 128x72; W: SM_W(st) 128x72.
// ---------------------------------------------------------------------------
#define GS 72
#define SM_A(st)  ((st)*9216)
#define SM_W(st)  (18432 + (st)*9216)
#define GSM_BYTES 73728

template<int MODE>
__global__ __launch_bounds__(256, 2) void gemm_tc(
    const __half* __restrict__ Ah, const __half* __restrict__ Wth,
    const float* __restrict__ bias, float* __restrict__ outF,
    __half* __restrict__ oqh, __half* __restrict__ okh, __half* __restrict__ ovh)
{
    int t    = threadIdx.x;
    int lane = t & 31, wid = t >> 5;
    int wm   = wid >> 1, wn = wid & 1;
    int m0   = blockIdx.y * 128, n0 = blockIdx.x * 128;
    int tg   = lane & 3, gp = lane >> 2;
    int z    = (MODE == 0) ? blockIdx.z : 3;
    size_t wbase = (size_t)z * Dd * Dd;

    uint32_t smb = smaddr(dynsm);

    int aRow = lane & 15, aColH = (lane >> 4) * 8;
    int bRow = ((lane >> 4) & 1) * 8 + (lane & 7);
    int bColH = ((lane >> 3) & 1) * 8;
    int aoff = (wm * 32 + aRow) * GS + aColH;
    int boff0 = (wn * 64 + bRow) * GS + bColH;

    // stage: A 1024 + W 1024 chunks of 16B => 8 per thread
    auto stage_load = [&](int st, int k0) {
        #pragma unroll
        for (int e = 0; e < 8; e++) {
            int id = t + e * 256;
            uint32_t dst;
            const __half* src;
            if (id < 1024) {
                int r = id >> 3, c = id & 7;
                src = Ah + (size_t)(m0 + r) * Dd + k0 + c * 8;
                dst = smb + 2 * (SM_A(st) + r * GS + c * 8);
            } else {
                int id2 = id - 1024;
                int r = id2 >> 3, c = id2 & 7;
                src = Wth + wbase + (size_t)(n0 + r) * Dd + k0 + c * 8;
                dst = smb + 2 * (SM_W(st) + r * GS + c * 8);
            }
            cpa16(dst, src);
        }
        CP_COMMIT();
    };

    float acc[2][8][4] = {};

    stage_load(0, 0);
    for (int it = 0; it < 16; it++) {
        int cur = it & 1;
        if (it < 15) { stage_load(cur ^ 1, (it + 1) * 64); CP_WAIT(1); }
        else         { CP_WAIT(0); }
        __syncthreads();

        #pragma unroll
        for (int kh = 0; kh < 4; kh++) {
            uint32_t fah[2][4];
            #pragma unroll
            for (int mi = 0; mi < 2; mi++) {
                uint32_t ah_ = smb + 2 * (SM_A(cur) + aoff + mi * 16 * GS + kh * 16);
                LDSM4(fah[mi][0], fah[mi][1], fah[mi][2], fah[mi][3], ah_);
            }
            #pragma unroll
            for (int pair = 0; pair < 4; pair++) {
                uint32_t bh_ = smb + 2 * (SM_W(cur) + boff0 + pair * 16 * GS + kh * 16);
                uint32_t t0, t1, t2, t3;
                LDSM4(t0, t1, t2, t3, bh_);
                #pragma unroll
                for (int mi = 0; mi < 2; mi++) {
                    MMA16816R(acc[mi][2*pair],     fah[mi], t0, t1);
                    MMA16816R(acc[mi][2*pair + 1], fah[mi], t2, t3);
                }
            }
        }
        __syncthreads();
    }

    // ---- epilogue
    #pragma unroll
    for (int mi = 0; mi < 2; mi++) {
        int r1 = m0 + wm * 32 + mi * 16 + gp;
        #pragma unroll
        for (int ni = 0; ni < 8; ni++) {
            int cn = n0 + wn * 64 + ni * 8 + tg * 2;
            if (MODE == 1) {
                float b0 = bias[cn], b1 = bias[cn + 1];
                outF[(size_t)r1 * Dd + cn]           = acc[mi][ni][0] + b0;
                outF[(size_t)r1 * Dd + cn + 1]       = acc[mi][ni][1] + b1;
                outF[(size_t)(r1 + 8) * Dd + cn]     = acc[mi][ni][2] + b0;
                outF[(size_t)(r1 + 8) * Dd + cn + 1] = acc[mi][ni][3] + b1;
            } else if (z == 0) {
                // Q: pre-scale by 1/8 (exact power of two)
                *(uint32_t*)&oqh[(size_t)r1 * Dd + cn] =
                    pack2h(0.125f * acc[mi][ni][0], 0.125f * acc[mi][ni][1]);
                *(uint32_t*)&oqh[(size_t)(r1 + 8) * Dd + cn] =
                    pack2h(0.125f * acc[mi][ni][2], 0.125f * acc[mi][ni][3]);
            } else if (z == 1) {
                *(uint32_t*)&okh[(size_t)r1 * Dd + cn] =
                    pack2h(acc[mi][ni][0], acc[mi][ni][1]);
                *(uint32_t*)&okh[(size_t)(r1 + 8) * Dd + cn] =
                    pack2h(acc[mi][ni][2], acc[mi][ni][3]);
            } else {
                // V transposed: out[((b*16+h)*64 + d)][s], m=(b,s), n=(h,d)
                #pragma unroll
                for (int rr = 0; rr < 2; rr++) {
                    int m = r1 + rr * 8;
                    int bI = m >> 11, s = m & 2047;
                    #pragma unroll
                    for (int cc = 0; cc < 2; cc++) {
                        int n = cn + cc;
                        int hI = n >> 6, d = n & 63;
                        size_t idx = ((size_t)(bI * Hh + hI) * HDd + d) * Ss + s;
                        ovh[idx] = __float2half_rn(acc[mi][ni][rr * 2 + cc]);
                    }
                }
            }
        }
    }
}

// ---------------------------------------------------------------------------
// MMA flash attention (causal), pure fp16 operands, fp32 accum.
// K double-buffered, V single-buffered with post-sync prefetch. Q pre-scaled.
// smem halves: Kh[st]: st*4608 (64x72); Vh: 9216. Total 27648 B; 4 blocks/SM.
// ---------------------------------------------------------------------------
#define VS 72
#define K_OFF(st) ((st) * 4608)
#define V_OFF     9216
#define ASM_BYTES 27648

__global__ __launch_bounds__(128, 4) void attn_mma_kernel(
    const __half* __restrict__ Qh, const __half* __restrict__ Kh,
    const __half* __restrict__ Vth, __half* __restrict__ Ch)
{
    int t    = threadIdx.x;
    int lane = t & 31, w = t >> 5;
    int tg   = lane & 3, gp = lane >> 2;
    int qt   = (int)gridDim.x - 1 - (int)blockIdx.x;   // longest first
    int bh   = blockIdx.y;
    int b    = bh >> 4, h = bh & 15;
    int q0   = qt * 64;
    int rowL0 = w * 16 + gp;

    uint32_t smb = smaddr(dynsm);
    int bRow = ((lane >> 4) & 1) * 8 + (lane & 7);
    int bColH = ((lane >> 3) & 1) * 8;

    const __half* kbh0 = Kh + ((size_t)(b * Ss)) * Dd + h * HDd;
    const __half* vbh0 = Vth + ((size_t)(b * Hh + h) * HDd) * Ss;

    // 512 x 16B chunks each: 4 per thread
    auto stageK = [&](int kt, int st) {
        #pragma unroll
        for (int e = 0; e < 4; e++) {
            int id = t + e * 128;
            int r = id >> 3, c = id & 7;
            cpa16(smb + 2 * (K_OFF(st) + r * VS + c * 8),
                  kbh0 + (size_t)(kt * 64 + r) * Dd + c * 8);
        }
    };
    auto stageV = [&](int kt) {
        #pragma unroll
        for (int e = 0; e < 4; e++) {
            int id = t + e * 128;
            int r = id >> 3, c = id & 7;
            cpa16(smb + 2 * (V_OFF + r * VS + c * 8),
                  vbh0 + (size_t)r * Ss + kt * 64 + c * 8);
        }
    };

    // ---- Q fragments from global (hi only, pre-scaled)
    uint32_t qhf[4][4];
    {
        const __half* qbh = Qh + ((size_t)(b * Ss + q0 + rowL0)) * Dd + h * HDd;
        #pragma unroll
        for (int s = 0; s < 4; s++) {
            int kc = s * 16 + tg * 2;
            qhf[s][0] = *(const uint32_t*)&qbh[kc];
            qhf[s][1] = *(const uint32_t*)&qbh[(size_t)8 * Dd + kc];
            qhf[s][2] = *(const uint32_t*)&qbh[kc + 8];
            qhf[s][3] = *(const uint32_t*)&qbh[(size_t)8 * Dd + kc + 8];
        }
    }

    float m0 = -1e30f, m1 = -1e30f;
    float l0 = 0.f,    l1 = 0.f;
    float o[8][4] = {};

    stageK(0, 0);
    stageV(0);
    CP_COMMIT();
    if (1 <= qt) stageK(1, 1);
    CP_COMMIT();

    for (int kt = 0; kt <= qt; kt++) {
        const bool diag = (kt == qt);
        const int st = kt & 1;
        if (kt < qt) CP_WAIT(1);   // drains K(kt)+V(kt)
        else         CP_WAIT(0);   // diag: drain everything
        __syncthreads();

        // ---- S = Q K^T (single term)
        float sc[8][4];
        #pragma unroll
        for (int ni = 0; ni < 8; ni++)
            sc[ni][0] = sc[ni][1] = sc[ni][2] = sc[ni][3] = 0.f;
        #pragma unroll
        for (int s = 0; s < 4; s++) {
            #pragma unroll
            for (int p = 0; p < 4; p++) {
                uint32_t kh_ = smb + 2 * (K_OFF(st) + (p * 16 + bRow) * VS + s * 16 + bColH);
                uint32_t t0, t1, t2, t3;
                LDSM4(t0, t1, t2, t3, kh_);
                MMA16816R(sc[2*p],     qhf[s], t0, t1);
                MMA16816R(sc[2*p + 1], qhf[s], t2, t3);
            }
        }

        // ---- mask + row max (scores already scaled via Q)
        float mx0 = -1e30f, mx1 = -1e30f;
        #pragma unroll
        for (int ni = 0; ni < 8; ni++) {
            int c0 = ni * 8 + tg * 2;
            float s0 = sc[ni][0], s1 = sc[ni][1];
            float s2 = sc[ni][2], s3 = sc[ni][3];
            if (diag) {
                if (c0     > rowL0)     s0 = -1e30f;
                if (c0 + 1 > rowL0)     s1 = -1e30f;
                if (c0     > rowL0 + 8) s2 = -1e30f;
                if (c0 + 1 > rowL0 + 8) s3 = -1e30f;
            }
            sc[ni][0] = s0; sc[ni][1] = s1; sc[ni][2] = s2; sc[ni][3] = s3;
            mx0 = fmaxf(mx0, fmaxf(s0, s1));
            mx1 = fmaxf(mx1, fmaxf(s2, s3));
        }
        mx0 = fmaxf(mx0, __shfl_xor_sync(0xffffffffu, mx0, 1));
        mx0 = fmaxf(mx0, __shfl_xor_sync(0xffffffffu, mx0, 2));
        mx1 = fmaxf(mx1, __shfl_xor_sync(0xffffffffu, mx1, 1));
        mx1 = fmaxf(mx1, __shfl_xor_sync(0xffffffffu, mx1, 2));

        float mn0 = fmaxf(m0, mx0), mn1 = fmaxf(m1, mx1);
        float a0 = __expf(m0 - mn0), a1 = __expf(m1 - mn1);
        m0 = mn0; m1 = mn1;
        l0 *= a0; l1 *= a1;
        #pragma unroll
        for (int ni = 0; ni < 8; ni++) {
            o[ni][0] *= a0; o[ni][1] *= a0;
            o[ni][2] *= a1; o[ni][3] *= a1;
        }

        // ---- P = exp(S - m)
        #pragma unroll
        for (int ni = 0; ni < 8; ni++) {
            float p0 = __expf(sc[ni][0] - m0);
            float p1 = __expf(sc[ni][1] - m0);
            float p2 = __expf(sc[ni][2] - m1);
            float p3 = __expf(sc[ni][3] - m1);
            l0 += p0 + p1; l1 += p2 + p3;
            sc[ni][0] = p0; sc[ni][1] = p1; sc[ni][2] = p2; sc[ni][3] = p3;
        }

        // ---- O += P V
        #pragma unroll
        for (int s = 0; s < 4; s++) {
            uint32_t pah[4];
            pah[0] = pack2h(sc[2*s][0],     sc[2*s][1]);
            pah[1] = pack2h(sc[2*s][2],     sc[2*s][3]);
            pah[2] = pack2h(sc[2*s + 1][0], sc[2*s + 1][1]);
            pah[3] = pack2h(sc[2*s + 1][2], sc[2*s + 1][3]);
            #pragma unroll
            for (int p = 0; p < 4; p++) {
                uint32_t vh_ = smb + 2 * (V_OFF + (p * 16 + bRow) * VS + s * 16 + bColH);
                uint32_t t0, t1, t2, t3;
                LDSM4(t0, t1, t2, t3, vh_);
                MMA16816R(o[2*p],     pah, t0, t1);
                MMA16816R(o[2*p + 1], pah, t2, t3);
            }
        }
        __syncthreads();    // everyone done with V(kt), K(kt)

        if (kt < qt) {
            stageV(kt + 1);
            CP_COMMIT();
            if (kt + 2 <= qt) stageK(kt + 2, (kt + 2) & 1);
            CP_COMMIT();
        }
    }

    // ---- finalize + fp16 ctx output
    l0 += __shfl_xor_sync(0xffffffffu, l0, 1);
    l0 += __shfl_xor_sync(0xffffffffu, l0, 2);
    l1 += __shfl_xor_sync(0xffffffffu, l1, 1);
    l1 += __shfl_xor_sync(0xffffffffu, l1, 2);
    float inv0 = 1.f / l0, inv1 = 1.f / l1;

    __half* obh = Ch + ((size_t)(b * Ss + q0 + rowL0)) * Dd + h * HDd;
    #pragma unroll
    for (int ni = 0; ni < 8; ni++) {
        int c = ni * 8 + tg * 2;
        *(uint32_t*)&obh[c] = pack2h(o[ni][0] * inv0, o[ni][1] * inv0);
        *(uint32_t*)&obh[(size_t)8 * Dd + c] = pack2h(o[ni][2] * inv1, o[ni][3] * inv1);
    }
}

// ---------------------------------------------------------------------------
extern "C" void kernel_launch(void* const* d_in, const int* in_sizes, int n_in,
                              void* d_out, int out_size)
{
    const float* x  = (const float*)d_in[0];
    const float* Wq = (const float*)d_in[1];
    const float* Wk = (const float*)d_in[2];
    const float* Wv = (const float*)d_in[3];
    const float* Wo = (const float*)d_in[4];
    const float* bo = (const float*)d_in[5];
    float* out = (float*)d_out;

    __half *ah, *qh, *kh, *vh, *wth;
    cudaGetSymbolAddress((void**)&ah, g_ah);
    cudaGetSymbolAddress((void**)&qh, g_qh);
    cudaGetSymbolAddress((void**)&kh, g_kh);
    cudaGetSymbolAddress((void**)&vh, g_vh);
    cudaGetSymbolAddress((void**)&wth, g_wth);

    cudaFuncSetAttribute(gemm_tc<0>, cudaFuncAttributeMaxDynamicSharedMemorySize, GSM_BYTES);
    cudaFuncSetAttribute(gemm_tc<1>, cudaFuncAttributeMaxDynamicSharedMemorySize, GSM_BYTES);
    cudaFuncSetAttribute(attn_mma_kernel, cudaFuncAttributeMaxDynamicSharedMemorySize, ASM_BYTES);

    const int NX = Mrows * Dd;

    tofp16_kernel<<<NX / 256, 256>>>(x, ah, NX);
    splitW_kernel<<<dim3(32, 32, 4), dim3(32, 8)>>>(Wq, Wk, Wv, Wo, wth);

    // fused QKV projections (z selects weight/output)
    gemm_tc<0><<<dim3(8, 64, 3), 256, GSM_BYTES>>>(
        ah, wth, nullptr, nullptr, qh, kh, vh);

    // attention writes fp16 ctx into ah (x is dead now)
    attn_mma_kernel<<<dim3(Ss / 64, Bb * Hh), 128, ASM_BYTES>>>(
        qh, kh, vh, ah);

    // output projection
    gemm_tc<1><<<dim3(8, 64), 256, GSM_BYTES>>>(
        ah, wth, bo, out, nullptr, nullptr, nullptr);
}